// round 1
// baseline (speedup 1.0000x reference)
#include <cuda_runtime.h>

// Shapes (fixed by the problem)
#define BB 16
#define NN 64
#define SS 2048
#define DD 1024
#define TT 768

// ---------------- scratch (device globals; no allocation allowed) ----------
__device__ float g_tok[(size_t)BB * SS * DD];     // projected tokens (B,S,D)
__device__ float g_attn[(size_t)BB * NN * SS];    // scores -> attn in place
__device__ float g_routed[(size_t)BB * NN * DD];  // attn @ tok
__device__ float g_cat[(size_t)BB * NN * 2 * DD]; // [ps_n, in_n]
__device__ float g_cat2[(size_t)BB * NN * 2 * DD];// [r*ps_n, in_n]
__device__ float g_u[(size_t)BB * NN * DD];       // update gate
__device__ float g_new[(size_t)BB * NN * DD];     // pre-output-LN state

// ---------------- 64x64 tile, 4x4/thread fp32 GEMM core --------------------
// A is MxK row-major (lda = K stride). If BT: B is (64 rows x K) row-major
// (both operands K-contiguous, C = A * B^T). Else: B is KxN row-major.
// Block = 256 threads. K must be a multiple of 16; all tiles full (shapes
// here are multiples of 64).
template<bool BT>
__device__ __forceinline__ void gemm64(const float* __restrict__ A,
                                       const float* __restrict__ Bp,
                                       int lda, int ldb, int K,
                                       float (&acc)[4][4]) {
    __shared__ float As[16][68];
    __shared__ float Bs[16][68];
    const int tid = threadIdx.x;
    const int tx = tid & 15;
    const int ty = tid >> 4;
    const int lr = tid >> 2;          // 0..63 (row for A / B^T loads)
    const int lk = (tid & 3) << 2;    // k offset within 16-wide tile

    for (int k0 = 0; k0 < K; k0 += 16) {
        float4 av = *reinterpret_cast<const float4*>(A + (size_t)lr * lda + k0 + lk);
        As[lk + 0][lr] = av.x; As[lk + 1][lr] = av.y;
        As[lk + 2][lr] = av.z; As[lk + 3][lr] = av.w;
        if (BT) {
            float4 bv = *reinterpret_cast<const float4*>(Bp + (size_t)lr * ldb + k0 + lk);
            Bs[lk + 0][lr] = bv.x; Bs[lk + 1][lr] = bv.y;
            Bs[lk + 2][lr] = bv.z; Bs[lk + 3][lr] = bv.w;
        } else {
            const int bk = tid >> 4;          // 0..15
            const int bn = (tid & 15) << 2;   // 0..60
            float4 bv = *reinterpret_cast<const float4*>(Bp + (size_t)(k0 + bk) * ldb + bn);
            *reinterpret_cast<float4*>(&Bs[bk][bn]) = bv;
        }
        __syncthreads();
#pragma unroll
        for (int kk = 0; kk < 16; ++kk) {
            float4 a = *reinterpret_cast<const float4*>(&As[kk][ty << 2]);
            float4 b = *reinterpret_cast<const float4*>(&Bs[kk][tx << 2]);
            float ar[4] = {a.x, a.y, a.z, a.w};
            float br[4] = {b.x, b.y, b.z, b.w};
#pragma unroll
            for (int i = 0; i < 4; ++i)
#pragma unroll
                for (int j = 0; j < 4; ++j)
                    acc[i][j] += ar[i] * br[j];
        }
        __syncthreads();
    }
}

// ---------------- reductions ------------------------------------------------
__device__ __forceinline__ float warpSum(float v) {
#pragma unroll
    for (int o = 16; o; o >>= 1) v += __shfl_xor_sync(0xffffffffu, v, o);
    return v;
}
__device__ __forceinline__ float warpMax(float v) {
#pragma unroll
    for (int o = 16; o; o >>= 1) v = fmaxf(v, __shfl_xor_sync(0xffffffffu, v, o));
    return v;
}

// ---------------- kernel 1: tok = tokens @ W_proj + b_proj ------------------
__global__ __launch_bounds__(256) void k_proj(const float* __restrict__ X,
                                              const float* __restrict__ W,
                                              const float* __restrict__ bias) {
    const int cb = blockIdx.x << 6;
    const size_t rb = (size_t)blockIdx.y << 6;
    float acc[4][4] = {};
    gemm64<false>(X + rb * TT, W + cb, TT, DD, TT, acc);
    const int tx = threadIdx.x & 15, ty = threadIdx.x >> 4;
#pragma unroll
    for (int i = 0; i < 4; ++i) {
        size_t r = rb + (ty << 2) + i;
#pragma unroll
        for (int j = 0; j < 4; ++j) {
            int c = cb + (tx << 2) + j;
            g_tok[r * DD + c] = acc[i][j] + bias[c];
        }
    }
}

// ---------------- kernel 2: scores = ps @ tok^T / sqrt(D) -------------------
__global__ __launch_bounds__(256) void k_scores(const float* __restrict__ PS) {
    const int b = blockIdx.z;
    const int sb = blockIdx.x << 6;
    float acc[4][4] = {};
    const float* A  = PS   + (size_t)b * NN * DD;
    const float* Bp = g_tok + (size_t)b * SS * DD + (size_t)sb * DD;
    gemm64<true>(A, Bp, DD, DD, DD, acc);
    float* C = g_attn + (size_t)b * NN * SS;
    const int tx = threadIdx.x & 15, ty = threadIdx.x >> 4;
    const float sc = 0.03125f; // 1/sqrt(1024)
#pragma unroll
    for (int i = 0; i < 4; ++i)
#pragma unroll
        for (int j = 0; j < 4; ++j)
            C[(size_t)((ty << 2) + i) * SS + sb + (tx << 2) + j] = acc[i][j] * sc;
}

// ---------------- kernel 3: softmax over S (row = 2048) ---------------------
__global__ __launch_bounds__(256) void k_softmax() {
    float* x = g_attn + (size_t)blockIdx.x * SS;
    const int tid = threadIdx.x;
    __shared__ float red[8];
    __shared__ float red2[8];

    float4 v0 = reinterpret_cast<float4*>(x)[tid];
    float4 v1 = reinterpret_cast<float4*>(x)[tid + 256];
    float m = fmaxf(fmaxf(fmaxf(v0.x, v0.y), fmaxf(v0.z, v0.w)),
                    fmaxf(fmaxf(v1.x, v1.y), fmaxf(v1.z, v1.w)));
    m = warpMax(m);
    if ((tid & 31) == 0) red[tid >> 5] = m;
    __syncthreads();
    m = red[0];
#pragma unroll
    for (int i = 1; i < 8; ++i) m = fmaxf(m, red[i]);

    v0.x = expf(v0.x - m); v0.y = expf(v0.y - m);
    v0.z = expf(v0.z - m); v0.w = expf(v0.w - m);
    v1.x = expf(v1.x - m); v1.y = expf(v1.y - m);
    v1.z = expf(v1.z - m); v1.w = expf(v1.w - m);
    float s = v0.x + v0.y + v0.z + v0.w + v1.x + v1.y + v1.z + v1.w;
    s = warpSum(s);
    if ((tid & 31) == 0) red2[tid >> 5] = s;
    __syncthreads();
    s = 0.f;
#pragma unroll
    for (int i = 0; i < 8; ++i) s += red2[i];
    const float inv = 1.0f / s;

    v0.x *= inv; v0.y *= inv; v0.z *= inv; v0.w *= inv;
    v1.x *= inv; v1.y *= inv; v1.z *= inv; v1.w *= inv;
    reinterpret_cast<float4*>(x)[tid] = v0;
    reinterpret_cast<float4*>(x)[tid + 256] = v1;
}

// ---------------- kernel 4: routed = attn @ tok ------------------------------
__global__ __launch_bounds__(256) void k_routed() {
    const int b = blockIdx.z;
    const int cb = blockIdx.x << 6;
    float acc[4][4] = {};
    gemm64<false>(g_attn + (size_t)b * NN * SS,
                  g_tok + (size_t)b * SS * DD + cb, SS, DD, SS, acc);
    float* C = g_routed + (size_t)b * NN * DD;
    const int tx = threadIdx.x & 15, ty = threadIdx.x >> 4;
#pragma unroll
    for (int i = 0; i < 4; ++i)
#pragma unroll
        for (int j = 0; j < 4; ++j)
            C[(size_t)((ty << 2) + i) * DD + cb + (tx << 2) + j] = acc[i][j];
}

// ---------------- kernel 5: two LayerNorms -> concat buffers ----------------
// rows [0,1024): ps_n = LN(prev)   -> g_cat[:, 0:1024]
// rows [1024,2048): in_n = LN(routed) -> g_cat[:, 1024:2048] AND g_cat2 same
__global__ __launch_bounds__(256) void k_ln_cat(const float* __restrict__ PS,
                                                const float* __restrict__ gs,
                                                const float* __restrict__ bs,
                                                const float* __restrict__ gi,
                                                const float* __restrict__ bi) {
    const int row = blockIdx.x;
    const bool isInput = row >= BB * NN;
    const int r = isInput ? row - BB * NN : row;
    const float* x = isInput ? (g_routed + (size_t)r * DD) : (PS + (size_t)r * DD);
    const float* gamma = isInput ? gi : gs;
    const float* beta  = isInput ? bi : bs;
    const int tid = threadIdx.x;
    __shared__ float s1[8];
    __shared__ float s2[8];

    float4 v = reinterpret_cast<const float4*>(x)[tid];
    float sum = v.x + v.y + v.z + v.w;
    float sq  = v.x * v.x + v.y * v.y + v.z * v.z + v.w * v.w;
    sum = warpSum(sum);
    sq  = warpSum(sq);
    if ((tid & 31) == 0) { s1[tid >> 5] = sum; s2[tid >> 5] = sq; }
    __syncthreads();
    sum = 0.f; sq = 0.f;
#pragma unroll
    for (int i = 0; i < 8; ++i) { sum += s1[i]; sq += s2[i]; }
    const float mean = sum * (1.0f / DD);
    const float var  = sq * (1.0f / DD) - mean * mean;
    const float inv  = rsqrtf(var + 1e-5f);

    float4 gv = reinterpret_cast<const float4*>(gamma)[tid];
    float4 bv = reinterpret_cast<const float4*>(beta)[tid];
    float4 y;
    y.x = (v.x - mean) * inv * gv.x + bv.x;
    y.y = (v.y - mean) * inv * gv.y + bv.y;
    y.z = (v.z - mean) * inv * gv.z + bv.z;
    y.w = (v.w - mean) * inv * gv.w + bv.w;

    const size_t off = (size_t)r * (2 * DD) + (isInput ? DD : 0);
    *reinterpret_cast<float4*>(&g_cat[off + (tid << 2)]) = y;
    if (isInput)
        *reinterpret_cast<float4*>(&g_cat2[off + (tid << 2)]) = y;
}

// ---------------- kernel 6: u and r gates (r folded into r*ps_n) ------------
__global__ __launch_bounds__(256) void k_gates(const float* __restrict__ Wu,
                                               const float* __restrict__ bu,
                                               const float* __restrict__ Wr,
                                               const float* __restrict__ br) {
    const int gate = blockIdx.z;
    const int cb = blockIdx.x << 6;
    const size_t rb = (size_t)blockIdx.y << 6;
    const float* W = gate ? Wr : Wu;
    const float* bias = gate ? br : bu;
    float acc[4][4] = {};
    gemm64<false>(g_cat + rb * (2 * DD), W + cb, 2 * DD, DD, 2 * DD, acc);
    const int tx = threadIdx.x & 15, ty = threadIdx.x >> 4;
#pragma unroll
    for (int i = 0; i < 4; ++i) {
        const size_t r = rb + (ty << 2) + i;
#pragma unroll
        for (int j = 0; j < 4; ++j) {
            const int c = cb + (tx << 2) + j;
            const float sv = 1.0f / (1.0f + expf(-(acc[i][j] + bias[c])));
            if (gate == 0)
                g_u[r * DD + c] = sv;
            else
                g_cat2[r * (2 * DD) + c] = sv * g_cat[r * (2 * DD) + c];
        }
    }
}

// ---------------- kernel 7: cand + gated combine -----------------------------
__global__ __launch_bounds__(256) void k_cand(const float* __restrict__ Wn,
                                              const float* __restrict__ bn,
                                              const float* __restrict__ PS) {
    const int cb = blockIdx.x << 6;
    const size_t rb = (size_t)blockIdx.y << 6;
    float acc[4][4] = {};
    gemm64<false>(g_cat2 + rb * (2 * DD), Wn + cb, 2 * DD, DD, 2 * DD, acc);
    const int tx = threadIdx.x & 15, ty = threadIdx.x >> 4;
#pragma unroll
    for (int i = 0; i < 4; ++i) {
        const size_t r = rb + (ty << 2) + i;
#pragma unroll
        for (int j = 0; j < 4; ++j) {
            const int c = cb + (tx << 2) + j;
            const size_t idx = r * DD + c;
            const float cand = tanhf(acc[i][j] + bn[c]);
            const float u = g_u[idx];
            g_new[idx] = (1.0f - u) * PS[idx] + u * cand;
        }
    }
}

// ---------------- kernel 8: output LayerNorm -> d_out -----------------------
__global__ __launch_bounds__(256) void k_ln_out(const float* __restrict__ go,
                                                const float* __restrict__ bo,
                                                float* __restrict__ out) {
    const int r = blockIdx.x;
    const float* x = g_new + (size_t)r * DD;
    const int tid = threadIdx.x;
    __shared__ float s1[8];
    __shared__ float s2[8];

    float4 v = reinterpret_cast<const float4*>(x)[tid];
    float sum = v.x + v.y + v.z + v.w;
    float sq  = v.x * v.x + v.y * v.y + v.z * v.z + v.w * v.w;
    sum = warpSum(sum);
    sq  = warpSum(sq);
    if ((tid & 31) == 0) { s1[tid >> 5] = sum; s2[tid >> 5] = sq; }
    __syncthreads();
    sum = 0.f; sq = 0.f;
#pragma unroll
    for (int i = 0; i < 8; ++i) { sum += s1[i]; sq += s2[i]; }
    const float mean = sum * (1.0f / DD);
    const float var  = sq * (1.0f / DD) - mean * mean;
    const float inv  = rsqrtf(var + 1e-5f);

    float4 gv = reinterpret_cast<const float4*>(go)[tid];
    float4 bv = reinterpret_cast<const float4*>(bo)[tid];
    float4 y;
    y.x = (v.x - mean) * inv * gv.x + bv.x;
    y.y = (v.y - mean) * inv * gv.y + bv.y;
    y.z = (v.z - mean) * inv * gv.z + bv.z;
    y.w = (v.w - mean) * inv * gv.w + bv.w;
    reinterpret_cast<float4*>(out + (size_t)r * DD)[tid] = y;
}

// ---------------- launch -----------------------------------------------------
extern "C" void kernel_launch(void* const* d_in, const int* in_sizes, int n_in,
                              void* d_out, int out_size) {
    (void)in_sizes; (void)n_in; (void)out_size;
    const float* prev = (const float*)d_in[0];
    const float* toks = (const float*)d_in[1];
    const float* Wp   = (const float*)d_in[2];
    const float* bp   = (const float*)d_in[3];
    const float* gs   = (const float*)d_in[4];
    const float* bs   = (const float*)d_in[5];
    const float* gi   = (const float*)d_in[6];
    const float* bi   = (const float*)d_in[7];
    const float* go   = (const float*)d_in[8];
    const float* bo   = (const float*)d_in[9];
    const float* Wu   = (const float*)d_in[10];
    const float* bu   = (const float*)d_in[11];
    const float* Wr   = (const float*)d_in[12];
    const float* br   = (const float*)d_in[13];
    const float* Wn   = (const float*)d_in[14];
    const float* bn   = (const float*)d_in[15];
    float* out = (float*)d_out;

    const dim3 blk(256);
    k_proj   <<<dim3(DD / 64, (BB * SS) / 64), blk>>>(toks, Wp, bp);
    k_scores <<<dim3(SS / 64, 1, BB), blk>>>(prev);
    k_softmax<<<BB * NN, 256>>>();
    k_routed <<<dim3(DD / 64, 1, BB), blk>>>();
    k_ln_cat <<<2 * BB * NN, 256>>>(prev, gs, bs, gi, bi);
    k_gates  <<<dim3(DD / 64, (BB * NN) / 64, 2), blk>>>(Wu, bu, Wr, br);
    k_cand   <<<dim3(DD / 64, (BB * NN) / 64), blk>>>(Wn, bn, prev);
    k_ln_out <<<BB * NN, 256>>>(go, bo, out);
}

// round 2
// speedup vs baseline: 1.6924x; 1.6924x over previous
#include <cuda_runtime.h>
#include <cuda_bf16.h>
#include <stdint.h>

// Shapes (fixed)
#define B_  16
#define NS  64
#define SQ  2048
#define DM  1024
#define TK  768

// ---------------- scratch (device globals) ----------------------------------
__device__ __align__(16) __nv_bfloat16 g_tokens_h[(size_t)B_*SQ*TK];
__device__ __align__(16) __nv_bfloat16 g_tokens_l[(size_t)B_*SQ*TK];
__device__ __align__(16) __nv_bfloat16 g_Wp_h[TK*DM],   g_Wp_l[TK*DM];
__device__ __align__(16) __nv_bfloat16 g_Wu_h[2*DM*DM], g_Wu_l[2*DM*DM];
__device__ __align__(16) __nv_bfloat16 g_Wr_h[2*DM*DM], g_Wr_l[2*DM*DM];
__device__ __align__(16) __nv_bfloat16 g_Wn_h[2*DM*DM], g_Wn_l[2*DM*DM];
__device__ __align__(16) __nv_bfloat16 g_ps_h[B_*NS*DM], g_ps_l[B_*NS*DM];
__device__ __align__(16) __nv_bfloat16 g_tok_h[(size_t)B_*SQ*DM];
__device__ __align__(16) __nv_bfloat16 g_tok_l[(size_t)B_*SQ*DM];
__device__ float g_scores[(size_t)B_*NS*SQ];
__device__ __align__(16) __nv_bfloat16 g_attn_h[B_*NS*SQ], g_attn_l[B_*NS*SQ];
__device__ float g_routed[B_*NS*DM];
__device__ __align__(16) __nv_bfloat16 g_cat_h[B_*NS*2*DM],  g_cat_l[B_*NS*2*DM];
__device__ __align__(16) __nv_bfloat16 g_cat2_h[B_*NS*2*DM], g_cat2_l[B_*NS*2*DM];
__device__ float g_u[B_*NS*DM];
__device__ float g_new[B_*NS*DM];

// ---------------- helpers ----------------------------------------------------
__device__ __forceinline__ void split1(float v, __nv_bfloat16& h, __nv_bfloat16& l) {
    h = __float2bfloat16_rn(v);
    l = __float2bfloat16_rn(v - __bfloat162float(h));
}
__device__ __forceinline__ unsigned s32(const void* p) {
    return (unsigned)__cvta_generic_to_shared(p);
}
__device__ __forceinline__ void cp16(unsigned dst, const void* src) {
    asm volatile("cp.async.cg.shared.global [%0], [%1], 16;\n" :: "r"(dst), "l"(src) : "memory");
}
__device__ __forceinline__ void cp_commit() { asm volatile("cp.async.commit_group;\n" ::); }
__device__ __forceinline__ void ldm_x4(uint32_t* r, unsigned a) {
    asm volatile("ldmatrix.sync.aligned.m8n8.x4.shared.b16 {%0,%1,%2,%3}, [%4];\n"
                 : "=r"(r[0]), "=r"(r[1]), "=r"(r[2]), "=r"(r[3]) : "r"(a));
}
__device__ __forceinline__ void ldm_x4_t(uint32_t* r, unsigned a) {
    asm volatile("ldmatrix.sync.aligned.m8n8.x4.trans.shared.b16 {%0,%1,%2,%3}, [%4];\n"
                 : "=r"(r[0]), "=r"(r[1]), "=r"(r[2]), "=r"(r[3]) : "r"(a));
}
__device__ __forceinline__ void mma16816(float* c, const uint32_t* a, const uint32_t* b) {
    asm volatile("mma.sync.aligned.m16n8k16.row.col.f32.bf16.bf16.f32 "
                 "{%0,%1,%2,%3}, {%4,%5,%6,%7}, {%8,%9}, {%0,%1,%2,%3};\n"
                 : "+f"(c[0]), "+f"(c[1]), "+f"(c[2]), "+f"(c[3])
                 : "r"(a[0]), "r"(a[1]), "r"(a[2]), "r"(a[3]), "r"(b[0]), "r"(b[1]));
}
__device__ __forceinline__ float warpSum(float v) {
#pragma unroll
    for (int o = 16; o; o >>= 1) v += __shfl_xor_sync(0xffffffffu, v, o);
    return v;
}
__device__ __forceinline__ float warpMax(float v) {
#pragma unroll
    for (int o = 16; o; o >>= 1) v = fmaxf(v, __shfl_xor_sync(0xffffffffu, v, o));
    return v;
}

// ---------------- fused epilogues --------------------------------------------
// 0: tok split (+bias)  1: scores scale  2: routed  3: u gate  4: r gate  5: cand
template<int EPI>
__device__ __forceinline__ void epi(float a, size_t gr, int c,
                                    const float* __restrict__ bias,
                                    const float* __restrict__ aux) {
    if constexpr (EPI == 0) {
        float v = a + bias[c];
        size_t i = gr * DM + c;
        split1(v, g_tok_h[i], g_tok_l[i]);
    } else if constexpr (EPI == 1) {
        g_scores[gr * SQ + c] = a * 0.03125f;
    } else if constexpr (EPI == 2) {
        g_routed[gr * DM + c] = a;
    } else if constexpr (EPI == 3) {
        g_u[gr * DM + c] = 1.0f / (1.0f + expf(-(a + bias[c])));
    } else if constexpr (EPI == 4) {
        float s = 1.0f / (1.0f + expf(-(a + bias[c])));
        size_t i = gr * (2 * DM) + c;
        float ps = __bfloat162float(g_cat_h[i]) + __bfloat162float(g_cat_l[i]);
        split1(s * ps, g_cat2_h[i], g_cat2_l[i]);
    } else {
        float t = tanhf(a + bias[c]);
        size_t i = gr * DM + c;
        float u = g_u[i];
        g_new[i] = (1.0f - u) * aux[i] + u * t;
    }
}

// ---------------- split-bf16 tensor-core GEMM --------------------------------
// A: M x K row-major (K contiguous), split into Ah/Al.
// BT=true : B stored N x K (K contiguous)  -> TN, ldmatrix non-trans
// BT=false: B stored K x N (N contiguous)  -> NN, ldmatrix .trans
// C = Ah*Bh + Ah*Bl + Al*Bh  (fp32 accum), fused epilogue EPI.
template<int BM, int BN, int WM, int WN, bool BT, int EPI>
__global__ __launch_bounds__(256, 1)
void gemm_split(const __nv_bfloat16* __restrict__ Ah, const __nv_bfloat16* __restrict__ Al,
                const __nv_bfloat16* __restrict__ Bh, const __nv_bfloat16* __restrict__ Bl,
                int lda, int ldb, int K,
                long long zA, long long zB, int rowz,
                const float* __restrict__ bias, const float* __restrict__ aux)
{
    constexpr int BK  = 16;
    constexpr int WMs = BM / WM;
    constexpr int MT  = WM / 16, NT = WN / 8;
    constexpr int AST = BK + 8;     // 24
    constexpr int BNP = BN + 8;     // 136

    __shared__ __align__(16) __nv_bfloat16 As[2][2][BM][AST];
    constexpr int BS_ELE = BT ? (2 * 2 * BN * AST) : (2 * 2 * BK * BNP);
    __shared__ __align__(16) __nv_bfloat16 Bs[BS_ELE];

    const int tid = threadIdx.x, lane = tid & 31, wid = tid >> 5;
    const int wm = wid % WMs, wn = wid / WMs;
    const int brow = blockIdx.y * BM, bcol = blockIdx.x * BN;
    const int z = blockIdx.z;

    const __nv_bfloat16* Aph = Ah + (size_t)z * zA + (size_t)brow * lda;
    const __nv_bfloat16* Apl = Al + (size_t)z * zA + (size_t)brow * lda;
    const __nv_bfloat16* Bph = Bh + (size_t)z * zB;
    const __nv_bfloat16* Bpl = Bl + (size_t)z * zB;

    float acc[MT][NT][4];
#pragma unroll
    for (int i = 0; i < MT; ++i)
#pragma unroll
        for (int j = 0; j < NT; ++j)
#pragma unroll
            for (int e = 0; e < 4; ++e) acc[i][j][e] = 0.f;

    auto bsOfs = [](int buf, int h, int r, int c) -> int {
        return BT ? (((buf * 2 + h) * BN + r) * AST + c)
                  : (((buf * 2 + h) * BK + r) * BNP + c);
    };

    auto loadSlab = [&](int buf, int k0) {
        // A slab: BM x 16, hi then lo
        for (int i = tid; i < BM * 4; i += 256) {
            int h = i / (BM * 2); int rem = i - h * BM * 2;
            int r = rem >> 1; int c8 = (rem & 1) * 8;
            const __nv_bfloat16* g = (h ? Apl : Aph) + (size_t)r * lda + k0 + c8;
            cp16(s32(&As[buf][h][r][c8]), g);
        }
        if (BT) {
            for (int i = tid; i < BN * 4; i += 256) {
                int h = i / (BN * 2); int rem = i - h * BN * 2;
                int n = rem >> 1; int c8 = (rem & 1) * 8;
                const __nv_bfloat16* g = (h ? Bpl : Bph) + (size_t)(bcol + n) * ldb + k0 + c8;
                cp16(s32(&Bs[bsOfs(buf, h, n, c8)]), g);
            }
        } else {
            constexpr int CH = BK * BN / 8;
            for (int i = tid; i < 2 * CH; i += 256) {
                int h = i / CH; int rem = i - h * CH;
                int k = rem / (BN / 8); int n8 = (rem % (BN / 8)) * 8;
                const __nv_bfloat16* g = (h ? Bpl : Bph) + (size_t)(k0 + k) * ldb + bcol + n8;
                cp16(s32(&Bs[bsOfs(buf, h, k, n8)]), g);
            }
        }
        cp_commit();
    };

    const int nk = K / BK;
    loadSlab(0, 0);

    for (int ks = 0; ks < nk; ++ks) {
        const int buf = ks & 1;
        if (ks + 1 < nk) {
            loadSlab(buf ^ 1, (ks + 1) * BK);
            asm volatile("cp.async.wait_group 1;\n" ::);
        } else {
            asm volatile("cp.async.wait_group 0;\n" ::);
        }
        __syncthreads();

        uint32_t afh[MT][4], afl[MT][4];
#pragma unroll
        for (int mt = 0; mt < MT; ++mt) {
            int row = wm * WM + mt * 16 + (lane & 15);
            int col = (lane >> 4) * 8;
            ldm_x4(afh[mt], s32(&As[buf][0][row][col]));
            ldm_x4(afl[mt], s32(&As[buf][1][row][col]));
        }
        uint32_t bfh[NT][2], bfl[NT][2];
#pragma unroll
        for (int p = 0; p < NT / 2; ++p) {
            int nbase = wn * WN + p * 16;
            uint32_t t[4];
            if (BT) {
                int r = nbase + (lane & 7) + ((lane >> 4) << 3);
                int c = ((lane >> 3) & 1) * 8;
                ldm_x4(t, s32(&Bs[bsOfs(buf, 0, r, c)]));
                bfh[2*p][0]=t[0]; bfh[2*p][1]=t[1]; bfh[2*p+1][0]=t[2]; bfh[2*p+1][1]=t[3];
                ldm_x4(t, s32(&Bs[bsOfs(buf, 1, r, c)]));
                bfl[2*p][0]=t[0]; bfl[2*p][1]=t[1]; bfl[2*p+1][0]=t[2]; bfl[2*p+1][1]=t[3];
            } else {
                int k = lane & 15;
                int nc = nbase + ((lane >> 4) << 3);
                ldm_x4_t(t, s32(&Bs[bsOfs(buf, 0, k, nc)]));
                bfh[2*p][0]=t[0]; bfh[2*p][1]=t[1]; bfh[2*p+1][0]=t[2]; bfh[2*p+1][1]=t[3];
                ldm_x4_t(t, s32(&Bs[bsOfs(buf, 1, k, nc)]));
                bfl[2*p][0]=t[0]; bfl[2*p][1]=t[1]; bfl[2*p+1][0]=t[2]; bfl[2*p+1][1]=t[3];
            }
        }
#pragma unroll
        for (int mt = 0; mt < MT; ++mt)
#pragma unroll
            for (int nt = 0; nt < NT; ++nt) {
                mma16816(acc[mt][nt], afh[mt], bfh[nt]);
                mma16816(acc[mt][nt], afh[mt], bfl[nt]);
                mma16816(acc[mt][nt], afl[mt], bfh[nt]);
            }
        __syncthreads();
    }

    // epilogue
#pragma unroll
    for (int mt = 0; mt < MT; ++mt) {
        int r0 = brow + wm * WM + mt * 16 + (lane >> 2);
#pragma unroll
        for (int nt = 0; nt < NT; ++nt) {
            int c0 = bcol + wn * WN + nt * 8 + ((lane & 3) << 1);
            size_t g0 = (size_t)z * rowz + r0;
            epi<EPI>(acc[mt][nt][0], g0,     c0,     bias, aux);
            epi<EPI>(acc[mt][nt][1], g0,     c0 + 1, bias, aux);
            epi<EPI>(acc[mt][nt][2], g0 + 8, c0,     bias, aux);
            epi<EPI>(acc[mt][nt][3], g0 + 8, c0 + 1, bias, aux);
        }
    }
}

// ---------------- fp32 -> (hi,lo) bf16 split ---------------------------------
__global__ __launch_bounds__(256) void k_split(const float* __restrict__ src,
                                               __nv_bfloat16* __restrict__ h,
                                               __nv_bfloat16* __restrict__ l, int n4) {
    int i = blockIdx.x * blockDim.x + threadIdx.x;
    if (i >= n4) return;
    float4 v = reinterpret_cast<const float4*>(src)[i];
    __nv_bfloat16 h0,h1,h2,h3,l0,l1,l2,l3;
    split1(v.x,h0,l0); split1(v.y,h1,l1); split1(v.z,h2,l2); split1(v.w,h3,l3);
    reinterpret_cast<__nv_bfloat162*>(h)[2*i]   = __nv_bfloat162(h0,h1);
    reinterpret_cast<__nv_bfloat162*>(h)[2*i+1] = __nv_bfloat162(h2,h3);
    reinterpret_cast<__nv_bfloat162*>(l)[2*i]   = __nv_bfloat162(l0,l1);
    reinterpret_cast<__nv_bfloat162*>(l)[2*i+1] = __nv_bfloat162(l2,l3);
}

// ---------------- softmax over S (2048) -> attn split ------------------------
__global__ __launch_bounds__(256) void k_softmax() {
    const size_t row = blockIdx.x;
    float* x = g_scores + row * SQ;
    const int tid = threadIdx.x;
    __shared__ float red[8], red2[8];

    float4 v0 = reinterpret_cast<float4*>(x)[tid];
    float4 v1 = reinterpret_cast<float4*>(x)[tid + 256];
    float m = fmaxf(fmaxf(fmaxf(v0.x, v0.y), fmaxf(v0.z, v0.w)),
                    fmaxf(fmaxf(v1.x, v1.y), fmaxf(v1.z, v1.w)));
    m = warpMax(m);
    if ((tid & 31) == 0) red[tid >> 5] = m;
    __syncthreads();
    m = red[0];
#pragma unroll
    for (int i = 1; i < 8; ++i) m = fmaxf(m, red[i]);

    v0.x = expf(v0.x - m); v0.y = expf(v0.y - m); v0.z = expf(v0.z - m); v0.w = expf(v0.w - m);
    v1.x = expf(v1.x - m); v1.y = expf(v1.y - m); v1.z = expf(v1.z - m); v1.w = expf(v1.w - m);
    float s = v0.x + v0.y + v0.z + v0.w + v1.x + v1.y + v1.z + v1.w;
    s = warpSum(s);
    if ((tid & 31) == 0) red2[tid >> 5] = s;
    __syncthreads();
    s = 0.f;
#pragma unroll
    for (int i = 0; i < 8; ++i) s += red2[i];
    const float inv = 1.0f / s;

    size_t b0 = row * SQ + (size_t)tid * 4;
    size_t b1 = b0 + 1024;
    float p[8] = {v0.x*inv, v0.y*inv, v0.z*inv, v0.w*inv,
                  v1.x*inv, v1.y*inv, v1.z*inv, v1.w*inv};
#pragma unroll
    for (int j = 0; j < 4; ++j) split1(p[j],     g_attn_h[b0 + j], g_attn_l[b0 + j]);
#pragma unroll
    for (int j = 0; j < 4; ++j) split1(p[4 + j], g_attn_h[b1 + j], g_attn_l[b1 + j]);
}

// ---------------- two LayerNorms -> cat / cat2 splits -------------------------
__global__ __launch_bounds__(256) void k_ln_cat(const float* __restrict__ PS,
                                                const float* __restrict__ gs,
                                                const float* __restrict__ bs,
                                                const float* __restrict__ gi,
                                                const float* __restrict__ bi) {
    const int rowId = blockIdx.x;
    const bool isInput = rowId >= B_ * NS;
    const int r = isInput ? rowId - B_ * NS : rowId;
    const float* x = isInput ? (g_routed + (size_t)r * DM) : (PS + (size_t)r * DM);
    const float* gamma = isInput ? gi : gs;
    const float* beta  = isInput ? bi : bs;
    const int tid = threadIdx.x;
    __shared__ float s1[8], s2[8];

    float4 v = reinterpret_cast<const float4*>(x)[tid];
    float sum = v.x + v.y + v.z + v.w;
    float sq  = v.x*v.x + v.y*v.y + v.z*v.z + v.w*v.w;
    sum = warpSum(sum); sq = warpSum(sq);
    if ((tid & 31) == 0) { s1[tid >> 5] = sum; s2[tid >> 5] = sq; }
    __syncthreads();
    sum = 0.f; sq = 0.f;
#pragma unroll
    for (int i = 0; i < 8; ++i) { sum += s1[i]; sq += s2[i]; }
    const float mean = sum * (1.0f / DM);
    const float var  = sq * (1.0f / DM) - mean * mean;
    const float inv  = rsqrtf(var + 1e-5f);

    float4 gv = reinterpret_cast<const float4*>(gamma)[tid];
    float4 bv = reinterpret_cast<const float4*>(beta)[tid];
    float y[4];
    y[0] = (v.x - mean) * inv * gv.x + bv.x;
    y[1] = (v.y - mean) * inv * gv.y + bv.y;
    y[2] = (v.z - mean) * inv * gv.z + bv.z;
    y[3] = (v.w - mean) * inv * gv.w + bv.w;

    const size_t off = (size_t)r * (2 * DM) + (isInput ? DM : 0) + (size_t)tid * 4;
#pragma unroll
    for (int j = 0; j < 4; ++j) {
        __nv_bfloat16 h, l;
        split1(y[j], h, l);
        g_cat_h[off + j] = h; g_cat_l[off + j] = l;
        if (isInput) { g_cat2_h[off + j] = h; g_cat2_l[off + j] = l; }
    }
}

// ---------------- output LayerNorm -------------------------------------------
__global__ __launch_bounds__(256) void k_ln_out(const float* __restrict__ go,
                                                const float* __restrict__ bo,
                                                float* __restrict__ out) {
    const int r = blockIdx.x;
    const float* x = g_new + (size_t)r * DM;
    const int tid = threadIdx.x;
    __shared__ float s1[8], s2[8];

    float4 v = reinterpret_cast<const float4*>(x)[tid];
    float sum = v.x + v.y + v.z + v.w;
    float sq  = v.x*v.x + v.y*v.y + v.z*v.z + v.w*v.w;
    sum = warpSum(sum); sq = warpSum(sq);
    if ((tid & 31) == 0) { s1[tid >> 5] = sum; s2[tid >> 5] = sq; }
    __syncthreads();
    sum = 0.f; sq = 0.f;
#pragma unroll
    for (int i = 0; i < 8; ++i) { sum += s1[i]; sq += s2[i]; }
    const float mean = sum * (1.0f / DM);
    const float var  = sq * (1.0f / DM) - mean * mean;
    const float inv  = rsqrtf(var + 1e-5f);

    float4 gv = reinterpret_cast<const float4*>(go)[tid];
    float4 bv = reinterpret_cast<const float4*>(bo)[tid];
    float4 y;
    y.x = (v.x - mean) * inv * gv.x + bv.x;
    y.y = (v.y - mean) * inv * gv.y + bv.y;
    y.z = (v.z - mean) * inv * gv.z + bv.z;
    y.w = (v.w - mean) * inv * gv.w + bv.w;
    reinterpret_cast<float4*>(out + (size_t)r * DM)[tid] = y;
}

// ---------------- launch -------------------------------------------------------
extern "C" void kernel_launch(void* const* d_in, const int* in_sizes, int n_in,
                              void* d_out, int out_size) {
    (void)in_sizes; (void)n_in; (void)out_size;
    const float* prev = (const float*)d_in[0];
    const float* toks = (const float*)d_in[1];
    const float* Wp   = (const float*)d_in[2];
    const float* bp   = (const float*)d_in[3];
    const float* gs   = (const float*)d_in[4];
    const float* bs   = (const float*)d_in[5];
    const float* gi   = (const float*)d_in[6];
    const float* bi   = (const float*)d_in[7];
    const float* go   = (const float*)d_in[8];
    const float* bo   = (const float*)d_in[9];
    const float* Wu   = (const float*)d_in[10];
    const float* bu   = (const float*)d_in[11];
    const float* Wr   = (const float*)d_in[12];
    const float* br   = (const float*)d_in[13];
    const float* Wn   = (const float*)d_in[14];
    const float* bn   = (const float*)d_in[15];
    float* out = (float*)d_out;

    __nv_bfloat16 *tok_h, *tok_l, *ps_h, *ps_l, *Wp_h, *Wp_l;
    __nv_bfloat16 *Wu_h, *Wu_l, *Wr_h, *Wr_l, *Wn_h, *Wn_l;
    __nv_bfloat16 *th, *tl, *ah, *al, *ch, *cl, *c2h, *c2l;
    cudaGetSymbolAddress((void**)&tok_h, g_tokens_h);
    cudaGetSymbolAddress((void**)&tok_l, g_tokens_l);
    cudaGetSymbolAddress((void**)&ps_h,  g_ps_h);
    cudaGetSymbolAddress((void**)&ps_l,  g_ps_l);
    cudaGetSymbolAddress((void**)&Wp_h,  g_Wp_h);
    cudaGetSymbolAddress((void**)&Wp_l,  g_Wp_l);
    cudaGetSymbolAddress((void**)&Wu_h,  g_Wu_h);
    cudaGetSymbolAddress((void**)&Wu_l,  g_Wu_l);
    cudaGetSymbolAddress((void**)&Wr_h,  g_Wr_h);
    cudaGetSymbolAddress((void**)&Wr_l,  g_Wr_l);
    cudaGetSymbolAddress((void**)&Wn_h,  g_Wn_h);
    cudaGetSymbolAddress((void**)&Wn_l,  g_Wn_l);
    cudaGetSymbolAddress((void**)&th,  g_tok_h);
    cudaGetSymbolAddress((void**)&tl,  g_tok_l);
    cudaGetSymbolAddress((void**)&ah,  g_attn_h);
    cudaGetSymbolAddress((void**)&al,  g_attn_l);
    cudaGetSymbolAddress((void**)&ch,  g_cat_h);
    cudaGetSymbolAddress((void**)&cl,  g_cat_l);
    cudaGetSymbolAddress((void**)&c2h, g_cat2_h);
    cudaGetSymbolAddress((void**)&c2l, g_cat2_l);

    // 1) splits
    k_split<<<(B_*SQ*TK/4 + 255)/256, 256>>>(toks, tok_h, tok_l, B_*SQ*TK/4);
    k_split<<<(B_*NS*DM/4 + 255)/256, 256>>>(prev, ps_h, ps_l, B_*NS*DM/4);
    k_split<<<(TK*DM/4   + 255)/256, 256>>>(Wp, Wp_h, Wp_l, TK*DM/4);
    k_split<<<(2*DM*DM/4 + 255)/256, 256>>>(Wu, Wu_h, Wu_l, 2*DM*DM/4);
    k_split<<<(2*DM*DM/4 + 255)/256, 256>>>(Wr, Wr_h, Wr_l, 2*DM*DM/4);
    k_split<<<(2*DM*DM/4 + 255)/256, 256>>>(Wn, Wn_h, Wn_l, 2*DM*DM/4);

    // 2) proj: tok = tokens @ W_proj + b   (M=32768,N=1024,K=768) NN
    gemm_split<128,128,32,64,false,0><<<dim3(DM/128, (B_*SQ)/128, 1), 256>>>(
        tok_h, tok_l, Wp_h, Wp_l, TK, DM, TK, 0, 0, 0, bp, nullptr);

    // 3) scores: ps @ tok^T (per batch, M=64,N=2048,K=1024) TN
    gemm_split<64,128,32,32,true,1><<<dim3(SQ/128, 1, B_), 256>>>(
        ps_h, ps_l, th, tl, DM, DM, DM,
        (long long)NS*DM, (long long)SQ*DM, NS, nullptr, nullptr);

    // 4) softmax -> attn split
    k_softmax<<<B_*NS, 256>>>();

    // 5) routed: attn @ tok (per batch, M=64,N=1024,K=2048) NN
    gemm_split<64,128,32,32,false,2><<<dim3(DM/128, 1, B_), 256>>>(
        ah, al, th, tl, SQ, DM, SQ,
        (long long)NS*SQ, (long long)SQ*DM, NS, nullptr, nullptr);

    // 6) LN(prev), LN(routed) -> cat / cat2 splits
    k_ln_cat<<<2*B_*NS, 256>>>(prev, gs, bs, gi, bi);

    // 7) gates u, r  (M=1024,N=1024,K=2048) NN
    gemm_split<128,128,32,64,false,3><<<dim3(DM/128, (B_*NS)/128, 1), 256>>>(
        ch, cl, Wu_h, Wu_l, 2*DM, DM, 2*DM, 0, 0, 0, bu, nullptr);
    gemm_split<128,128,32,64,false,4><<<dim3(DM/128, (B_*NS)/128, 1), 256>>>(
        ch, cl, Wr_h, Wr_l, 2*DM, DM, 2*DM, 0, 0, 0, br, nullptr);

    // 8) cand + gated combine
    gemm_split<128,128,32,64,false,5><<<dim3(DM/128, (B_*NS)/128, 1), 256>>>(
        c2h, c2l, Wn_h, Wn_l, 2*DM, DM, 2*DM, 0, 0, 0, bn, prev);

    // 9) output LN
    k_ln_out<<<B_*NS, 256>>>(go, bo, out);
}

// round 4
// speedup vs baseline: 2.5899x; 1.5303x over previous
#include <cuda_runtime.h>
#include <cuda_fp16.h>
#include <stdint.h>

// Shapes (fixed)
#define B_  16
#define NS  64
#define SQ  2048
#define DM  1024
#define TK  768

// ---------------- scratch (device globals) ----------------------------------
__device__ __align__(16) __half g_tokens_h[(size_t)B_*SQ*TK];            // A of proj (hi only)
__device__ __align__(16) __half g_Wp_h[TK*DM],   g_Wp_l[TK*DM];          // B of proj
__device__ __align__(16) __half g_Wu_h[2*DM*DM], g_Wu_l[2*DM*DM];
__device__ __align__(16) __half g_Wr_h[2*DM*DM], g_Wr_l[2*DM*DM];
__device__ __align__(16) __half g_Wn_h[2*DM*DM], g_Wn_l[2*DM*DM];
__device__ __align__(16) __half g_ps_h[B_*NS*DM];                        // A of scores
__device__ __align__(16) __half g_tok_h[(size_t)B_*SQ*DM];               // B of scores/routed
__device__ __align__(16) __half g_tok_l[(size_t)B_*SQ*DM];
__device__ float g_scores[(size_t)B_*NS*SQ];
__device__ __align__(16) __half g_attn_h[B_*NS*SQ];                      // A of routed
__device__ float g_routed[B_*NS*DM];
__device__ __align__(16) __half g_cat_h[B_*NS*2*DM];                     // A of gates
__device__ __align__(16) __half g_cat2_h[B_*NS*2*DM];                    // A of cand
__device__ float g_u[B_*NS*DM];
__device__ float g_new[B_*NS*DM];

// ---------------- helpers ----------------------------------------------------
__device__ __forceinline__ void splitH(float v, __half& h, __half& l) {
    h = __float2half_rn(v);
    l = __float2half_rn(v - __half2float(h));
}
__device__ __forceinline__ unsigned s32(const void* p) {
    return (unsigned)__cvta_generic_to_shared(p);
}
__device__ __forceinline__ void cp16(unsigned dst, const void* src) {
    asm volatile("cp.async.cg.shared.global [%0], [%1], 16;\n" :: "r"(dst), "l"(src) : "memory");
}
__device__ __forceinline__ void cp_commit() { asm volatile("cp.async.commit_group;\n" ::); }
__device__ __forceinline__ void ldm_x4(uint32_t* r, unsigned a) {
    asm volatile("ldmatrix.sync.aligned.m8n8.x4.shared.b16 {%0,%1,%2,%3}, [%4];\n"
                 : "=r"(r[0]), "=r"(r[1]), "=r"(r[2]), "=r"(r[3]) : "r"(a));
}
__device__ __forceinline__ void ldm_x4_t(uint32_t* r, unsigned a) {
    asm volatile("ldmatrix.sync.aligned.m8n8.x4.trans.shared.b16 {%0,%1,%2,%3}, [%4];\n"
                 : "=r"(r[0]), "=r"(r[1]), "=r"(r[2]), "=r"(r[3]) : "r"(a));
}
__device__ __forceinline__ void mma16816(float* c, const uint32_t* a, const uint32_t* b) {
    asm volatile("mma.sync.aligned.m16n8k16.row.col.f32.f16.f16.f32 "
                 "{%0,%1,%2,%3}, {%4,%5,%6,%7}, {%8,%9}, {%0,%1,%2,%3};\n"
                 : "+f"(c[0]), "+f"(c[1]), "+f"(c[2]), "+f"(c[3])
                 : "r"(a[0]), "r"(a[1]), "r"(a[2]), "r"(a[3]), "r"(b[0]), "r"(b[1]));
}
__device__ __forceinline__ float warpSum(float v) {
#pragma unroll
    for (int o = 16; o; o >>= 1) v += __shfl_xor_sync(0xffffffffu, v, o);
    return v;
}
__device__ __forceinline__ float warpMax(float v) {
#pragma unroll
    for (int o = 16; o; o >>= 1) v = fmaxf(v, __shfl_xor_sync(0xffffffffu, v, o));
    return v;
}

// ---------------- fused epilogues --------------------------------------------
// 0: tok split(+bias)  1: scores scale  2: routed  3: u gate  4: r gate  5: cand
template<int EPI>
__device__ __forceinline__ void epi(float a, size_t gr, int c,
                                    const float* __restrict__ bias,
                                    const float* __restrict__ aux) {
    if constexpr (EPI == 0) {
        float v = a + bias[c];
        size_t i = gr * DM + c;
        splitH(v, g_tok_h[i], g_tok_l[i]);
    } else if constexpr (EPI == 1) {
        g_scores[gr * SQ + c] = a * 0.03125f;
    } else if constexpr (EPI == 2) {
        g_routed[gr * DM + c] = a;
    } else if constexpr (EPI == 3) {
        g_u[gr * DM + c] = 1.0f / (1.0f + expf(-(a + bias[c])));
    } else if constexpr (EPI == 4) {
        float s = 1.0f / (1.0f + expf(-(a + bias[c])));
        size_t i = gr * (2 * DM) + c;
        float ps = __half2float(g_cat_h[i]);
        g_cat2_h[i] = __float2half_rn(s * ps);
    } else {
        float t = tanhf(a + bias[c]);
        size_t i = gr * DM + c;
        float u = g_u[i];
        g_new[i] = (1.0f - u) * aux[i] + u * t;
    }
}

// ---------------- 2-pass split-fp16 tensor-core GEMM -------------------------
// A: M x K row-major fp16 (hi only).
// BT=true : B stored N x K (K contiguous, hi+lo)  -> ldmatrix non-trans
// BT=false: B stored K x N (N contiguous, hi+lo)  -> ldmatrix .trans
// C = A*Bh + A*Bl (fp32 accum), fused epilogue EPI. BK=32, double buffered.
template<int BM, int BN, int WM, int WN, bool BT, int EPI>
__global__ __launch_bounds__(256, 1)
void gemm2(const __half* __restrict__ A,
           const __half* __restrict__ Bh, const __half* __restrict__ Bl,
           int lda, int ldb, int K,
           long long zA, long long zB, int rowz,
           const float* __restrict__ bias, const float* __restrict__ aux)
{
    constexpr int BK  = 32;
    constexpr int WMs = BM / WM;
    constexpr int MT  = WM / 16, NT = WN / 8;
    constexpr int AST = BK + 8;     // 40
    constexpr int BST = BK + 8;     // 40 (BT=true layout)
    constexpr int BNP = BN + 8;     // (BT=false layout)

    extern __shared__ __align__(16) __half sm[];
    __half* As = sm;                                    // [2][BM][AST]
    __half* Bs = sm + 2 * BM * AST;                     // BT: [2][2][BN][BST]  else [2][2][BK][BNP]

    const int tid = threadIdx.x, lane = tid & 31, wid = tid >> 5;
    const int wm = wid % WMs, wn = wid / WMs;
    const int brow = blockIdx.y * BM, bcol = blockIdx.x * BN;
    const int z = blockIdx.z;

    const __half* Ap  = A  + (size_t)z * zA + (size_t)brow * lda;
    const __half* Bph = Bh + (size_t)z * zB;
    const __half* Bpl = Bl + (size_t)z * zB;

    float acc[MT][NT][4];
#pragma unroll
    for (int i = 0; i < MT; ++i)
#pragma unroll
        for (int j = 0; j < NT; ++j)
#pragma unroll
            for (int e = 0; e < 4; ++e) acc[i][j][e] = 0.f;

    auto aOfs = [](int buf, int r, int c) -> int { return (buf * BM + r) * AST + c; };
    auto bOfs = [](int buf, int h, int r, int c) -> int {
        return BT ? (((buf * 2 + h) * BN + r) * BST + c)
                  : (((buf * 2 + h) * BK + r) * BNP + c);
    };

    auto loadSlab = [&](int buf, int k0) {
        // A: BM rows x 32 halves (hi only) = BM*4 cp16
        for (int i = tid; i < BM * 4; i += 256) {
            int r = i >> 2, c = (i & 3) * 8;
            cp16(s32(&As[aOfs(buf, r, c)]), Ap + (size_t)r * lda + k0 + c);
        }
        if (BT) {
            for (int i = tid; i < BN * 8; i += 256) {
                int h = i / (BN * 4); int rem = i - h * BN * 4;
                int n = rem >> 2, c = (rem & 3) * 8;
                const __half* g = (h ? Bpl : Bph) + (size_t)(bcol + n) * ldb + k0 + c;
                cp16(s32(&Bs[bOfs(buf, h, n, c)]), g);
            }
        } else {
            constexpr int CH = BK * BN / 8;       // cp16 per half
            for (int i = tid; i < 2 * CH; i += 256) {
                int h = i / CH; int rem = i - h * CH;
                int k = rem / (BN / 8); int n8 = (rem % (BN / 8)) * 8;
                const __half* g = (h ? Bpl : Bph) + (size_t)(k0 + k) * ldb + bcol + n8;
                cp16(s32(&Bs[bOfs(buf, h, k, n8)]), g);
            }
        }
        cp_commit();
    };

    const int nk = K / BK;
    loadSlab(0, 0);

    for (int ks = 0; ks < nk; ++ks) {
        const int buf = ks & 1;
        if (ks + 1 < nk) {
            loadSlab(buf ^ 1, (ks + 1) * BK);
            asm volatile("cp.async.wait_group 1;\n" ::);
        } else {
            asm volatile("cp.async.wait_group 0;\n" ::);
        }
        __syncthreads();

#pragma unroll
        for (int kk2 = 0; kk2 < 2; ++kk2) {
            uint32_t af[MT][4];
#pragma unroll
            for (int mt = 0; mt < MT; ++mt) {
                int row = wm * WM + mt * 16 + (lane & 15);
                int col = kk2 * 16 + (lane >> 4) * 8;
                ldm_x4(af[mt], s32(&As[aOfs(buf, row, col)]));
            }
            uint32_t bfh[NT][2], bfl[NT][2];
#pragma unroll
            for (int p = 0; p < NT / 2; ++p) {
                int nbase = wn * WN + p * 16;
                uint32_t t[4];
                if (BT) {
                    int r = nbase + (lane & 7) + ((lane >> 4) << 3);
                    int c = kk2 * 16 + ((lane >> 3) & 1) * 8;
                    ldm_x4(t, s32(&Bs[bOfs(buf, 0, r, c)]));
                    bfh[2*p][0]=t[0]; bfh[2*p][1]=t[1]; bfh[2*p+1][0]=t[2]; bfh[2*p+1][1]=t[3];
                    ldm_x4(t, s32(&Bs[bOfs(buf, 1, r, c)]));
                    bfl[2*p][0]=t[0]; bfl[2*p][1]=t[1]; bfl[2*p+1][0]=t[2]; bfl[2*p+1][1]=t[3];
                } else {
                    int k = kk2 * 16 + (lane & 15);
                    int nc = nbase + ((lane >> 4) << 3);
                    ldm_x4_t(t, s32(&Bs[bOfs(buf, 0, k, nc)]));
                    bfh[2*p][0]=t[0]; bfh[2*p][1]=t[1]; bfh[2*p+1][0]=t[2]; bfh[2*p+1][1]=t[3];
                    ldm_x4_t(t, s32(&Bs[bOfs(buf, 1, k, nc)]));
                    bfl[2*p][0]=t[0]; bfl[2*p][1]=t[1]; bfl[2*p+1][0]=t[2]; bfl[2*p+1][1]=t[3];
                }
            }
#pragma unroll
            for (int mt = 0; mt < MT; ++mt)
#pragma unroll
                for (int nt = 0; nt < NT; ++nt) {
                    mma16816(acc[mt][nt], af[mt], bfh[nt]);
                    mma16816(acc[mt][nt], af[mt], bfl[nt]);
                }
        }
        __syncthreads();
    }

    // epilogue
#pragma unroll
    for (int mt = 0; mt < MT; ++mt) {
        int r0 = brow + wm * WM + mt * 16 + (lane >> 2);
#pragma unroll
        for (int nt = 0; nt < NT; ++nt) {
            int c0 = bcol + wn * WN + nt * 8 + ((lane & 3) << 1);
            size_t g0 = (size_t)z * rowz + r0;
            epi<EPI>(acc[mt][nt][0], g0,     c0,     bias, aux);
            epi<EPI>(acc[mt][nt][1], g0,     c0 + 1, bias, aux);
            epi<EPI>(acc[mt][nt][2], g0 + 8, c0,     bias, aux);
            epi<EPI>(acc[mt][nt][3], g0 + 8, c0 + 1, bias, aux);
        }
    }
}

// ---------------- fp32 -> fp16 (hi only) --------------------------------------
__global__ __launch_bounds__(256) void k_split_h(const float* __restrict__ src,
                                                 __half* __restrict__ h, int n4) {
    int i = blockIdx.x * blockDim.x + threadIdx.x;
    if (i >= n4) return;
    float4 v = reinterpret_cast<const float4*>(src)[i];
    reinterpret_cast<__half2*>(h)[2*i]   = __half2(__float2half_rn(v.x), __float2half_rn(v.y));
    reinterpret_cast<__half2*>(h)[2*i+1] = __half2(__float2half_rn(v.z), __float2half_rn(v.w));
}

// ---------------- fp32 -> (hi,lo) fp16 ----------------------------------------
__global__ __launch_bounds__(256) void k_split2(const float* __restrict__ src,
                                                __half* __restrict__ h,
                                                __half* __restrict__ l, int n4) {
    int i = blockIdx.x * blockDim.x + threadIdx.x;
    if (i >= n4) return;
    float4 v = reinterpret_cast<const float4*>(src)[i];
    __half h0,h1,h2,h3,l0,l1,l2,l3;
    splitH(v.x,h0,l0); splitH(v.y,h1,l1); splitH(v.z,h2,l2); splitH(v.w,h3,l3);
    reinterpret_cast<__half2*>(h)[2*i]   = __half2(h0,h1);
    reinterpret_cast<__half2*>(h)[2*i+1] = __half2(h2,h3);
    reinterpret_cast<__half2*>(l)[2*i]   = __half2(l0,l1);
    reinterpret_cast<__half2*>(l)[2*i+1] = __half2(l2,l3);
}

// ---------------- softmax over S (2048) -> attn fp16 ---------------------------
__global__ __launch_bounds__(256) void k_softmax() {
    const size_t row = blockIdx.x;
    float* x = g_scores + row * SQ;
    const int tid = threadIdx.x;
    __shared__ float red[8], red2[8];

    float4 v0 = reinterpret_cast<float4*>(x)[tid];
    float4 v1 = reinterpret_cast<float4*>(x)[tid + 256];
    float m = fmaxf(fmaxf(fmaxf(v0.x, v0.y), fmaxf(v0.z, v0.w)),
                    fmaxf(fmaxf(v1.x, v1.y), fmaxf(v1.z, v1.w)));
    m = warpMax(m);
    if ((tid & 31) == 0) red[tid >> 5] = m;
    __syncthreads();
    m = red[0];
#pragma unroll
    for (int i = 1; i < 8; ++i) m = fmaxf(m, red[i]);

    v0.x = expf(v0.x - m); v0.y = expf(v0.y - m); v0.z = expf(v0.z - m); v0.w = expf(v0.w - m);
    v1.x = expf(v1.x - m); v1.y = expf(v1.y - m); v1.z = expf(v1.z - m); v1.w = expf(v1.w - m);
    float s = v0.x + v0.y + v0.z + v0.w + v1.x + v1.y + v1.z + v1.w;
    s = warpSum(s);
    if ((tid & 31) == 0) red2[tid >> 5] = s;
    __syncthreads();
    s = 0.f;
#pragma unroll
    for (int i = 0; i < 8; ++i) s += red2[i];
    const float inv = 1.0f / s;

    size_t b0 = row * SQ + (size_t)tid * 4;
    size_t b1 = b0 + 1024;
    g_attn_h[b0+0] = __float2half_rn(v0.x*inv); g_attn_h[b0+1] = __float2half_rn(v0.y*inv);
    g_attn_h[b0+2] = __float2half_rn(v0.z*inv); g_attn_h[b0+3] = __float2half_rn(v0.w*inv);
    g_attn_h[b1+0] = __float2half_rn(v1.x*inv); g_attn_h[b1+1] = __float2half_rn(v1.y*inv);
    g_attn_h[b1+2] = __float2half_rn(v1.z*inv); g_attn_h[b1+3] = __float2half_rn(v1.w*inv);
}

// ---------------- two LayerNorms -> cat / cat2 (fp16) --------------------------
__global__ __launch_bounds__(256) void k_ln_cat(const float* __restrict__ PS,
                                                const float* __restrict__ gs,
                                                const float* __restrict__ bs,
                                                const float* __restrict__ gi,
                                                const float* __restrict__ bi) {
    const int rowId = blockIdx.x;
    const bool isInput = rowId >= B_ * NS;
    const int r = isInput ? rowId - B_ * NS : rowId;
    const float* x = isInput ? (g_routed + (size_t)r * DM) : (PS + (size_t)r * DM);
    const float* gamma = isInput ? gi : gs;
    const float* beta  = isInput ? bi : bs;
    const int tid = threadIdx.x;
    __shared__ float s1[8], s2[8];

    float4 v = reinterpret_cast<const float4*>(x)[tid];
    float sum = v.x + v.y + v.z + v.w;
    float sq  = v.x*v.x + v.y*v.y + v.z*v.z + v.w*v.w;
    sum = warpSum(sum); sq = warpSum(sq);
    if ((tid & 31) == 0) { s1[tid >> 5] = sum; s2[tid >> 5] = sq; }
    __syncthreads();
    sum = 0.f; sq = 0.f;
#pragma unroll
    for (int i = 0; i < 8; ++i) { sum += s1[i]; sq += s2[i]; }
    const float mean = sum * (1.0f / DM);
    const float var  = sq * (1.0f / DM) - mean * mean;
    const float inv  = rsqrtf(var + 1e-5f);

    float4 gv = reinterpret_cast<const float4*>(gamma)[tid];
    float4 bv = reinterpret_cast<const float4*>(beta)[tid];
    float y[4];
    y[0] = (v.x - mean) * inv * gv.x + bv.x;
    y[1] = (v.y - mean) * inv * gv.y + bv.y;
    y[2] = (v.z - mean) * inv * gv.z + bv.z;
    y[3] = (v.w - mean) * inv * gv.w + bv.w;

    const size_t off = (size_t)r * (2 * DM) + (isInput ? DM : 0) + (size_t)tid * 4;
#pragma unroll
    for (int j = 0; j < 4; ++j) {
        __half h = __float2half_rn(y[j]);
        g_cat_h[off + j] = h;
        if (isInput) g_cat2_h[off + j] = h;
    }
}

// ---------------- output LayerNorm ---------------------------------------------
__global__ __launch_bounds__(256) void k_ln_out(const float* __restrict__ go,
                                                const float* __restrict__ bo,
                                                float* __restrict__ out) {
    const int r = blockIdx.x;
    const float* x = g_new + (size_t)r * DM;
    const int tid = threadIdx.x;
    __shared__ float s1[8], s2[8];

    float4 v = reinterpret_cast<const float4*>(x)[tid];
    float sum = v.x + v.y + v.z + v.w;
    float sq  = v.x*v.x + v.y*v.y + v.z*v.z + v.w*v.w;
    sum = warpSum(sum); sq = warpSum(sq);
    if ((tid & 31) == 0) { s1[tid >> 5] = sum; s2[tid >> 5] = sq; }
    __syncthreads();
    sum = 0.f; sq = 0.f;
#pragma unroll
    for (int i = 0; i < 8; ++i) { sum += s1[i]; sq += s2[i]; }
    const float mean = sum * (1.0f / DM);
    const float var  = sq * (1.0f / DM) - mean * mean;
    const float inv  = rsqrtf(var + 1e-5f);

    float4 gv = reinterpret_cast<const float4*>(go)[tid];
    float4 bv = reinterpret_cast<const float4*>(bo)[tid];
    float4 y;
    y.x = (v.x - mean) * inv * gv.x + bv.x;
    y.y = (v.y - mean) * inv * gv.y + bv.y;
    y.z = (v.z - mean) * inv * gv.z + bv.z;
    y.w = (v.w - mean) * inv * gv.w + bv.w;
    reinterpret_cast<float4*>(out + (size_t)r * DM)[tid] = y;
}

// ---------------- launch ---------------------------------------------------------
extern "C" void kernel_launch(void* const* d_in, const int* in_sizes, int n_in,
                              void* d_out, int out_size) {
    (void)in_sizes; (void)n_in; (void)out_size;
    const float* prev = (const float*)d_in[0];
    const float* toks = (const float*)d_in[1];
    const float* Wp   = (const float*)d_in[2];
    const float* bp   = (const float*)d_in[3];
    const float* gs   = (const float*)d_in[4];
    const float* bs   = (const float*)d_in[5];
    const float* gi   = (const float*)d_in[6];
    const float* bi   = (const float*)d_in[7];
    const float* go   = (const float*)d_in[8];
    const float* bo   = (const float*)d_in[9];
    const float* Wu   = (const float*)d_in[10];
    const float* bu   = (const float*)d_in[11];
    const float* Wr   = (const float*)d_in[12];
    const float* br   = (const float*)d_in[13];
    const float* Wn   = (const float*)d_in[14];
    const float* bn   = (const float*)d_in[15];
    float* out = (float*)d_out;

    __half *tok_h, *ps_h, *Wp_h, *Wp_l, *Wu_h, *Wu_l, *Wr_h, *Wr_l, *Wn_h, *Wn_l;
    __half *th, *tl, *ah, *ch, *c2h;
    cudaGetSymbolAddress((void**)&tok_h, g_tokens_h);
    cudaGetSymbolAddress((void**)&ps_h,  g_ps_h);
    cudaGetSymbolAddress((void**)&Wp_h,  g_Wp_h);
    cudaGetSymbolAddress((void**)&Wp_l,  g_Wp_l);
    cudaGetSymbolAddress((void**)&Wu_h,  g_Wu_h);
    cudaGetSymbolAddress((void**)&Wu_l,  g_Wu_l);
    cudaGetSymbolAddress((void**)&Wr_h,  g_Wr_h);
    cudaGetSymbolAddress((void**)&Wr_l,  g_Wr_l);
    cudaGetSymbolAddress((void**)&Wn_h,  g_Wn_h);
    cudaGetSymbolAddress((void**)&Wn_l,  g_Wn_l);
    cudaGetSymbolAddress((void**)&th,  g_tok_h);
    cudaGetSymbolAddress((void**)&tl,  g_tok_l);
    cudaGetSymbolAddress((void**)&ah,  g_attn_h);
    cudaGetSymbolAddress((void**)&ch,  g_cat_h);
    cudaGetSymbolAddress((void**)&c2h, g_cat2_h);

    // dynamic smem sizes (bytes)
    constexpr int SM_BIG    = (2*128*40 + 2*2*32*136) * 2;   // 55296  (128x128, BT=false)
    constexpr int SM_SCORES = (2*64*40  + 2*2*128*40) * 2;   // 51200  (64x128, BT=true)
    constexpr int SM_ROUTED = (2*64*40  + 2*2*32*136) * 2;   // 45056  (64x128, BT=false)
    cudaFuncSetAttribute((const void*)gemm2<128,128,64,32,false,0>, cudaFuncAttributeMaxDynamicSharedMemorySize, SM_BIG);
    cudaFuncSetAttribute((const void*)gemm2<64,128,32,32,true,1>,   cudaFuncAttributeMaxDynamicSharedMemorySize, SM_SCORES);
    cudaFuncSetAttribute((const void*)gemm2<64,128,32,32,false,2>,  cudaFuncAttributeMaxDynamicSharedMemorySize, SM_ROUTED);
    cudaFuncSetAttribute((const void*)gemm2<128,128,64,32,false,3>, cudaFuncAttributeMaxDynamicSharedMemorySize, SM_BIG);
    cudaFuncSetAttribute((const void*)gemm2<128,128,64,32,false,4>, cudaFuncAttributeMaxDynamicSharedMemorySize, SM_BIG);
    cudaFuncSetAttribute((const void*)gemm2<128,128,64,32,false,5>, cudaFuncAttributeMaxDynamicSharedMemorySize, SM_BIG);

    // 1) input conversions
    k_split_h<<<(B_*SQ*TK/4 + 255)/256, 256>>>(toks, tok_h, B_*SQ*TK/4);
    k_split_h<<<(B_*NS*DM/4 + 255)/256, 256>>>(prev, ps_h, B_*NS*DM/4);
    k_split2<<<(TK*DM/4   + 255)/256, 256>>>(Wp, Wp_h, Wp_l, TK*DM/4);
    k_split2<<<(2*DM*DM/4 + 255)/256, 256>>>(Wu, Wu_h, Wu_l, 2*DM*DM/4);
    k_split2<<<(2*DM*DM/4 + 255)/256, 256>>>(Wr, Wr_h, Wr_l, 2*DM*DM/4);
    k_split2<<<(2*DM*DM/4 + 255)/256, 256>>>(Wn, Wn_h, Wn_l, 2*DM*DM/4);

    // 2) proj: tok = tokens @ W_proj + b   (M=32768,N=1024,K=768) NN
    gemm2<128,128,64,32,false,0><<<dim3(DM/128, (B_*SQ)/128, 1), 256, SM_BIG>>>(
        tok_h, Wp_h, Wp_l, TK, DM, TK, 0, 0, 0, bp, nullptr);

    // 3) scores: ps @ tok^T (per batch, M=64,N=2048,K=1024) TN
    gemm2<64,128,32,32,true,1><<<dim3(SQ/128, 1, B_), 256, SM_SCORES>>>(
        ps_h, th, tl, DM, DM, DM,
        (long long)NS*DM, (long long)SQ*DM, NS, nullptr, nullptr);

    // 4) softmax -> attn fp16
    k_softmax<<<B_*NS, 256>>>();

    // 5) routed: attn @ tok (per batch, M=64,N=1024,K=2048) NN
    gemm2<64,128,32,32,false,2><<<dim3(DM/128, 1, B_), 256, SM_ROUTED>>>(
        ah, th, tl, SQ, DM, SQ,
        (long long)NS*SQ, (long long)SQ*DM, NS, nullptr, nullptr);

    // 6) LN(prev), LN(routed) -> cat / cat2
    k_ln_cat<<<2*B_*NS, 256>>>(prev, gs, bs, gi, bi);

    // 7) gates u, r  (M=1024,N=1024,K=2048) NN
    gemm2<128,128,64,32,false,3><<<dim3(DM/128, (B_*NS)/128, 1), 256, SM_BIG>>>(
        ch, Wu_h, Wu_l, 2*DM, DM, 2*DM, 0, 0, 0, bu, nullptr);
    gemm2<128,128,64,32,false,4><<<dim3(DM/128, (B_*NS)/128, 1), 256, SM_BIG>>>(
        ch, Wr_h, Wr_l, 2*DM, DM, 2*DM, 0, 0, 0, br, nullptr);

    // 8) cand + gated combine
    gemm2<128,128,64,32,false,5><<<dim3(DM/128, (B_*NS)/128, 1), 256, SM_BIG>>>(
        c2h, Wn_h, Wn_l, 2*DM, DM, 2*DM, 0, 0, 0, bn, prev);

    // 9) output LN
    k_ln_out<<<B_*NS, 256>>>(go, bo, out);
}

// round 5
// speedup vs baseline: 3.8249x; 1.4769x over previous
#include <cuda_runtime.h>
#include <cuda_fp16.h>
#include <stdint.h>

// Shapes (fixed)
#define B_  16
#define NS  64
#define SQ  2048
#define DM  1024
#define TK  768

// ---------------- scratch (device globals) ----------------------------------
__device__ __align__(16) __half g_tokens_h[(size_t)B_*SQ*TK];            // A of proj (hi only)
__device__ __align__(16) __half g_Wp_h[TK*DM],   g_Wp_l[TK*DM];          // B of proj
__device__ __align__(16) __half g_Wg_h[3*(size_t)2*DM*DM];               // [Wu | Wr | Wn] hi
__device__ __align__(16) __half g_Wg_l[3*(size_t)2*DM*DM];               // [Wu | Wr | Wn] lo
__device__ __align__(16) __half g_ps_h[B_*NS*DM];                        // A of scores
__device__ __align__(16) __half g_tok_h[(size_t)B_*SQ*DM];               // B of scores/routed
__device__ __align__(16) __half g_tok_l[(size_t)B_*SQ*DM];
__device__ __align__(16) float g_scores[(size_t)B_*NS*SQ];
__device__ __align__(16) __half g_attn_h[B_*NS*SQ];                      // A of routed
__device__ __align__(16) float g_routed[B_*NS*DM];
__device__ __align__(16) __half g_cat_h[B_*NS*2*DM];                     // A of gates
__device__ __align__(16) __half g_cat2_h[B_*NS*2*DM];                    // A of cand
__device__ __align__(16) float g_u[B_*NS*DM];
__device__ __align__(16) float g_new[B_*NS*DM];

// ---------------- helpers ----------------------------------------------------
__device__ __forceinline__ void splitH(float v, __half& h, __half& l) {
    h = __float2half_rn(v);
    l = __float2half_rn(v - __half2float(h));
}
__device__ __forceinline__ unsigned s32(const void* p) {
    return (unsigned)__cvta_generic_to_shared(p);
}
__device__ __forceinline__ void cp16(unsigned dst, const void* src) {
    asm volatile("cp.async.cg.shared.global [%0], [%1], 16;\n" :: "r"(dst), "l"(src) : "memory");
}
__device__ __forceinline__ void cp_commit() { asm volatile("cp.async.commit_group;\n" ::); }
__device__ __forceinline__ void ldm_x4(uint32_t* r, unsigned a) {
    asm volatile("ldmatrix.sync.aligned.m8n8.x4.shared.b16 {%0,%1,%2,%3}, [%4];\n"
                 : "=r"(r[0]), "=r"(r[1]), "=r"(r[2]), "=r"(r[3]) : "r"(a));
}
__device__ __forceinline__ void ldm_x4_t(uint32_t* r, unsigned a) {
    asm volatile("ldmatrix.sync.aligned.m8n8.x4.trans.shared.b16 {%0,%1,%2,%3}, [%4];\n"
                 : "=r"(r[0]), "=r"(r[1]), "=r"(r[2]), "=r"(r[3]) : "r"(a));
}
__device__ __forceinline__ void mma16816(float* c, const uint32_t* a, const uint32_t* b) {
    asm volatile("mma.sync.aligned.m16n8k16.row.col.f32.f16.f16.f32 "
                 "{%0,%1,%2,%3}, {%4,%5,%6,%7}, {%8,%9}, {%0,%1,%2,%3};\n"
                 : "+f"(c[0]), "+f"(c[1]), "+f"(c[2]), "+f"(c[3])
                 : "r"(a[0]), "r"(a[1]), "r"(a[2]), "r"(a[3]), "r"(b[0]), "r"(b[1]));
}
__device__ __forceinline__ float warpSum(float v) {
#pragma unroll
    for (int o = 16; o; o >>= 1) v += __shfl_xor_sync(0xffffffffu, v, o);
    return v;
}
__device__ __forceinline__ float warpMax(float v) {
#pragma unroll
    for (int o = 16; o; o >>= 1) v = fmaxf(v, __shfl_xor_sync(0xffffffffu, v, o));
    return v;
}

// ---------------- fused vectorized epilogues ----------------------------------
// EPI: 0=tok split(+bias)  1=scores scale  2=routed  34=u/r gates (z picks)  5=cand
template<int EPI>
__device__ __forceinline__ void epi2(float a0, float a1, size_t gr, int c, int z,
                                     const float* __restrict__ bias,
                                     const float* __restrict__ aux) {
    if constexpr (EPI == 0) {
        float v0 = a0 + bias[c], v1 = a1 + bias[c + 1];
        __half h0, l0, h1, l1;
        splitH(v0, h0, l0); splitH(v1, h1, l1);
        size_t i = gr * DM + c;
        *reinterpret_cast<__half2*>(&g_tok_h[i]) = __half2(h0, h1);
        *reinterpret_cast<__half2*>(&g_tok_l[i]) = __half2(l0, l1);
    } else if constexpr (EPI == 1) {
        *reinterpret_cast<float2*>(&g_scores[gr * SQ + c]) =
            make_float2(a0 * 0.03125f, a1 * 0.03125f);
    } else if constexpr (EPI == 2) {
        *reinterpret_cast<float2*>(&g_routed[gr * DM + c]) = make_float2(a0, a1);
    } else if constexpr (EPI == 34) {
        float s0 = 1.0f / (1.0f + expf(-(a0 + bias[c])));
        float s1 = 1.0f / (1.0f + expf(-(a1 + bias[c + 1])));
        if (z == 0) {
            *reinterpret_cast<float2*>(&g_u[gr * DM + c]) = make_float2(s0, s1);
        } else {
            size_t i = gr * (2 * DM) + c;
            __half2 ps = *reinterpret_cast<__half2*>(&g_cat_h[i]);
            *reinterpret_cast<__half2*>(&g_cat2_h[i]) =
                __half2(__float2half_rn(s0 * __half2float(ps.x)),
                        __float2half_rn(s1 * __half2float(ps.y)));
        }
    } else {
        size_t i = gr * DM + c;
        float2 u = *reinterpret_cast<const float2*>(&g_u[i]);
        float2 pv = *reinterpret_cast<const float2*>(&aux[i]);
        float t0 = tanhf(a0 + bias[c]), t1 = tanhf(a1 + bias[c + 1]);
        *reinterpret_cast<float2*>(&g_new[i]) =
            make_float2((1.0f - u.x) * pv.x + u.x * t0,
                        (1.0f - u.y) * pv.y + u.y * t1);
    }
}

// ---------------- 2-pass split-fp16 tensor-core GEMM -------------------------
// A: M x K row-major fp16 (hi only).
// BT=true : B stored N x K (K contiguous, hi+lo)  -> ldmatrix non-trans
// BT=false: B stored K x N (N contiguous, hi+lo)  -> ldmatrix .trans
// C = A*Bh + A*Bl (fp32 accum), fused epilogue EPI. BK=32, double buffered.
template<int BM, int BN, int WM, int WN, bool BT, int EPI>
__global__ __launch_bounds__(256, 2)
void gemm2(const __half* __restrict__ A,
           const __half* __restrict__ Bh, const __half* __restrict__ Bl,
           int lda, int ldb, int K,
           long long zA, long long zB, int rowz,
           const float* __restrict__ bias0, const float* __restrict__ bias1,
           const float* __restrict__ aux)
{
    constexpr int BK  = 32;
    constexpr int WMs = BM / WM;
    constexpr int MT  = WM / 16, NT = WN / 8;
    constexpr int AST = BK + 8;     // 40
    constexpr int BST = BK + 8;     // 40 (BT=true layout)
    constexpr int BNP = BN + 8;     // (BT=false layout)

    extern __shared__ __align__(16) __half sm[];
    __half* As = sm;                                    // [2][BM][AST]
    __half* Bs = sm + 2 * BM * AST;                     // BT: [2][2][BN][BST] else [2][2][BK][BNP]

    const int tid = threadIdx.x, lane = tid & 31, wid = tid >> 5;
    const int wm = wid % WMs, wn = wid / WMs;
    const int brow = blockIdx.y * BM, bcol = blockIdx.x * BN;
    const int z = blockIdx.z;

    const __half* Ap  = A  + (size_t)z * zA + (size_t)brow * lda;
    const __half* Bph = Bh + (size_t)z * zB;
    const __half* Bpl = Bl + (size_t)z * zB;

    float acc[MT][NT][4];
#pragma unroll
    for (int i = 0; i < MT; ++i)
#pragma unroll
        for (int j = 0; j < NT; ++j)
#pragma unroll
            for (int e = 0; e < 4; ++e) acc[i][j][e] = 0.f;

    auto aOfs = [](int buf, int r, int c) -> int { return (buf * BM + r) * AST + c; };
    auto bOfs = [](int buf, int h, int r, int c) -> int {
        return BT ? (((buf * 2 + h) * BN + r) * BST + c)
                  : (((buf * 2 + h) * BK + r) * BNP + c);
    };

    auto loadSlab = [&](int buf, int k0) {
        for (int i = tid; i < BM * 4; i += 256) {
            int r = i >> 2, c = (i & 3) * 8;
            cp16(s32(&As[aOfs(buf, r, c)]), Ap + (size_t)r * lda + k0 + c);
        }
        if (BT) {
            for (int i = tid; i < BN * 8; i += 256) {
                int h = i / (BN * 4); int rem = i - h * BN * 4;
                int n = rem >> 2, c = (rem & 3) * 8;
                const __half* g = (h ? Bpl : Bph) + (size_t)(bcol + n) * ldb + k0 + c;
                cp16(s32(&Bs[bOfs(buf, h, n, c)]), g);
            }
        } else {
            constexpr int CH = BK * BN / 8;
            for (int i = tid; i < 2 * CH; i += 256) {
                int h = i / CH; int rem = i - h * CH;
                int k = rem / (BN / 8); int n8 = (rem % (BN / 8)) * 8;
                const __half* g = (h ? Bpl : Bph) + (size_t)(k0 + k) * ldb + bcol + n8;
                cp16(s32(&Bs[bOfs(buf, h, k, n8)]), g);
            }
        }
        cp_commit();
    };

    const int nk = K / BK;
    loadSlab(0, 0);

    for (int ks = 0; ks < nk; ++ks) {
        const int buf = ks & 1;
        if (ks + 1 < nk) {
            loadSlab(buf ^ 1, (ks + 1) * BK);
            asm volatile("cp.async.wait_group 1;\n" ::);
        } else {
            asm volatile("cp.async.wait_group 0;\n" ::);
        }
        __syncthreads();

#pragma unroll
        for (int kk2 = 0; kk2 < 2; ++kk2) {
            uint32_t af[MT][4];
#pragma unroll
            for (int mt = 0; mt < MT; ++mt) {
                int row = wm * WM + mt * 16 + (lane & 15);
                int col = kk2 * 16 + (lane >> 4) * 8;
                ldm_x4(af[mt], s32(&As[aOfs(buf, row, col)]));
            }
            uint32_t bfh[NT][2], bfl[NT][2];
#pragma unroll
            for (int p = 0; p < NT / 2; ++p) {
                int nbase = wn * WN + p * 16;
                uint32_t t[4];
                if (BT) {
                    int r = nbase + (lane & 7) + ((lane >> 4) << 3);
                    int c = kk2 * 16 + ((lane >> 3) & 1) * 8;
                    ldm_x4(t, s32(&Bs[bOfs(buf, 0, r, c)]));
                    bfh[2*p][0]=t[0]; bfh[2*p][1]=t[1]; bfh[2*p+1][0]=t[2]; bfh[2*p+1][1]=t[3];
                    ldm_x4(t, s32(&Bs[bOfs(buf, 1, r, c)]));
                    bfl[2*p][0]=t[0]; bfl[2*p][1]=t[1]; bfl[2*p+1][0]=t[2]; bfl[2*p+1][1]=t[3];
                } else {
                    int k = kk2 * 16 + (lane & 15);
                    int nc = nbase + ((lane >> 4) << 3);
                    ldm_x4_t(t, s32(&Bs[bOfs(buf, 0, k, nc)]));
                    bfh[2*p][0]=t[0]; bfh[2*p][1]=t[1]; bfh[2*p+1][0]=t[2]; bfh[2*p+1][1]=t[3];
                    ldm_x4_t(t, s32(&Bs[bOfs(buf, 1, k, nc)]));
                    bfl[2*p][0]=t[0]; bfl[2*p][1]=t[1]; bfl[2*p+1][0]=t[2]; bfl[2*p+1][1]=t[3];
                }
            }
#pragma unroll
            for (int mt = 0; mt < MT; ++mt)
#pragma unroll
                for (int nt = 0; nt < NT; ++nt) {
                    mma16816(acc[mt][nt], af[mt], bfh[nt]);
                    mma16816(acc[mt][nt], af[mt], bfl[nt]);
                }
        }
        __syncthreads();
    }

    // epilogue (vectorized: pairs are contiguous columns)
    const float* bias = (z != 0 && bias1) ? bias1 : bias0;
#pragma unroll
    for (int mt = 0; mt < MT; ++mt) {
        int r0 = brow + wm * WM + mt * 16 + (lane >> 2);
#pragma unroll
        for (int nt = 0; nt < NT; ++nt) {
            int c0 = bcol + wn * WN + nt * 8 + ((lane & 3) << 1);
            size_t g0 = (size_t)z * rowz + r0;
            epi2<EPI>(acc[mt][nt][0], acc[mt][nt][1], g0,     c0, z, bias, aux);
            epi2<EPI>(acc[mt][nt][2], acc[mt][nt][3], g0 + 8, c0, z, bias, aux);
        }
    }
}

// ---------------- fp32 -> fp16 (hi only) --------------------------------------
__global__ __launch_bounds__(256) void k_split_h(const float* __restrict__ src,
                                                 __half* __restrict__ h, int n4) {
    int i = blockIdx.x * blockDim.x + threadIdx.x;
    if (i >= n4) return;
    float4 v = reinterpret_cast<const float4*>(src)[i];
    reinterpret_cast<__half2*>(h)[2*i]   = __half2(__float2half_rn(v.x), __float2half_rn(v.y));
    reinterpret_cast<__half2*>(h)[2*i+1] = __half2(__float2half_rn(v.z), __float2half_rn(v.w));
}

// ---------------- fp32 -> (hi,lo) fp16 ----------------------------------------
__global__ __launch_bounds__(256) void k_split2(const float* __restrict__ src,
                                                __half* __restrict__ h,
                                                __half* __restrict__ l, int n4) {
    int i = blockIdx.x * blockDim.x + threadIdx.x;
    if (i >= n4) return;
    float4 v = reinterpret_cast<const float4*>(src)[i];
    __half h0,h1,h2,h3,l0,l1,l2,l3;
    splitH(v.x,h0,l0); splitH(v.y,h1,l1); splitH(v.z,h2,l2); splitH(v.w,h3,l3);
    reinterpret_cast<__half2*>(h)[2*i]   = __half2(h0,h1);
    reinterpret_cast<__half2*>(h)[2*i+1] = __half2(h2,h3);
    reinterpret_cast<__half2*>(l)[2*i]   = __half2(l0,l1);
    reinterpret_cast<__half2*>(l)[2*i+1] = __half2(l2,l3);
}

// ---------------- 3 weights -> contiguous (hi,lo) fp16 -------------------------
__global__ __launch_bounds__(256) void k_split2w(const float* __restrict__ w0,
                                                 const float* __restrict__ w1,
                                                 const float* __restrict__ w2,
                                                 __half* __restrict__ h,
                                                 __half* __restrict__ l, int n4) {
    int i = blockIdx.x * blockDim.x + threadIdx.x;
    if (i >= n4) return;
    int z = blockIdx.y;
    const float* src = (z == 0) ? w0 : (z == 1) ? w1 : w2;
    size_t o = (size_t)z * n4 + i;
    float4 v = reinterpret_cast<const float4*>(src)[i];
    __half h0,h1,h2,h3,l0,l1,l2,l3;
    splitH(v.x,h0,l0); splitH(v.y,h1,l1); splitH(v.z,h2,l2); splitH(v.w,h3,l3);
    reinterpret_cast<__half2*>(h)[2*o]   = __half2(h0,h1);
    reinterpret_cast<__half2*>(h)[2*o+1] = __half2(h2,h3);
    reinterpret_cast<__half2*>(l)[2*o]   = __half2(l0,l1);
    reinterpret_cast<__half2*>(l)[2*o+1] = __half2(l2,l3);
}

// ---------------- softmax over S (2048) -> attn fp16 ---------------------------
__global__ __launch_bounds__(256) void k_softmax() {
    const size_t row = blockIdx.x;
    float* x = g_scores + row * SQ;
    const int tid = threadIdx.x;
    __shared__ float red[8], red2[8];

    float4 v0 = reinterpret_cast<float4*>(x)[tid];
    float4 v1 = reinterpret_cast<float4*>(x)[tid + 256];
    float m = fmaxf(fmaxf(fmaxf(v0.x, v0.y), fmaxf(v0.z, v0.w)),
                    fmaxf(fmaxf(v1.x, v1.y), fmaxf(v1.z, v1.w)));
    m = warpMax(m);
    if ((tid & 31) == 0) red[tid >> 5] = m;
    __syncthreads();
    m = red[0];
#pragma unroll
    for (int i = 1; i < 8; ++i) m = fmaxf(m, red[i]);

    v0.x = expf(v0.x - m); v0.y = expf(v0.y - m); v0.z = expf(v0.z - m); v0.w = expf(v0.w - m);
    v1.x = expf(v1.x - m); v1.y = expf(v1.y - m); v1.z = expf(v1.z - m); v1.w = expf(v1.w - m);
    float s = v0.x + v0.y + v0.z + v0.w + v1.x + v1.y + v1.z + v1.w;
    s = warpSum(s);
    if ((tid & 31) == 0) red2[tid >> 5] = s;
    __syncthreads();
    s = 0.f;
#pragma unroll
    for (int i = 0; i < 8; ++i) s += red2[i];
    const float inv = 1.0f / s;

    size_t b0 = row * SQ + (size_t)tid * 4;
    size_t b1 = b0 + 1024;
    *reinterpret_cast<__half2*>(&g_attn_h[b0]) =
        __half2(__float2half_rn(v0.x*inv), __float2half_rn(v0.y*inv));
    *reinterpret_cast<__half2*>(&g_attn_h[b0+2]) =
        __half2(__float2half_rn(v0.z*inv), __float2half_rn(v0.w*inv));
    *reinterpret_cast<__half2*>(&g_attn_h[b1]) =
        __half2(__float2half_rn(v1.x*inv), __float2half_rn(v1.y*inv));
    *reinterpret_cast<__half2*>(&g_attn_h[b1+2]) =
        __half2(__float2half_rn(v1.z*inv), __float2half_rn(v1.w*inv));
}

// ---------------- two LayerNorms -> cat / cat2 (fp16) --------------------------
__global__ __launch_bounds__(256) void k_ln_cat(const float* __restrict__ PS,
                                                const float* __restrict__ gs,
                                                const float* __restrict__ bs,
                                                const float* __restrict__ gi,
                                                const float* __restrict__ bi) {
    const int rowId = blockIdx.x;
    const bool isInput = rowId >= B_ * NS;
    const int r = isInput ? rowId - B_ * NS : rowId;
    const float* x = isInput ? (g_routed + (size_t)r * DM) : (PS + (size_t)r * DM);
    const float* gamma = isInput ? gi : gs;
    const float* beta  = isInput ? bi : bs;
    const int tid = threadIdx.x;
    __shared__ float s1[8], s2[8];

    float4 v = reinterpret_cast<const float4*>(x)[tid];
    float sum = v.x + v.y + v.z + v.w;
    float sq  = v.x*v.x + v.y*v.y + v.z*v.z + v.w*v.w;
    sum = warpSum(sum); sq = warpSum(sq);
    if ((tid & 31) == 0) { s1[tid >> 5] = sum; s2[tid >> 5] = sq; }
    __syncthreads();
    sum = 0.f; sq = 0.f;
#pragma unroll
    for (int i = 0; i < 8; ++i) { sum += s1[i]; sq += s2[i]; }
    const float mean = sum * (1.0f / DM);
    const float var  = sq * (1.0f / DM) - mean * mean;
    const float inv  = rsqrtf(var + 1e-5f);

    float4 gv = reinterpret_cast<const float4*>(gamma)[tid];
    float4 bv = reinterpret_cast<const float4*>(beta)[tid];
    __half h0 = __float2half_rn((v.x - mean) * inv * gv.x + bv.x);
    __half h1 = __float2half_rn((v.y - mean) * inv * gv.y + bv.y);
    __half h2 = __float2half_rn((v.z - mean) * inv * gv.z + bv.z);
    __half h3 = __float2half_rn((v.w - mean) * inv * gv.w + bv.w);

    const size_t off = (size_t)r * (2 * DM) + (isInput ? DM : 0) + (size_t)tid * 4;
    *reinterpret_cast<__half2*>(&g_cat_h[off])     = __half2(h0, h1);
    *reinterpret_cast<__half2*>(&g_cat_h[off + 2]) = __half2(h2, h3);
    if (isInput) {
        *reinterpret_cast<__half2*>(&g_cat2_h[off])     = __half2(h0, h1);
        *reinterpret_cast<__half2*>(&g_cat2_h[off + 2]) = __half2(h2, h3);
    }
}

// ---------------- output LayerNorm ---------------------------------------------
__global__ __launch_bounds__(256) void k_ln_out(const float* __restrict__ go,
                                                const float* __restrict__ bo,
                                                float* __restrict__ out) {
    const int r = blockIdx.x;
    const float* x = g_new + (size_t)r * DM;
    const int tid = threadIdx.x;
    __shared__ float s1[8], s2[8];

    float4 v = reinterpret_cast<const float4*>(x)[tid];
    float sum = v.x + v.y + v.z + v.w;
    float sq  = v.x*v.x + v.y*v.y + v.z*v.z + v.w*v.w;
    sum = warpSum(sum); sq = warpSum(sq);
    if ((tid & 31) == 0) { s1[tid >> 5] = sum; s2[tid >> 5] = sq; }
    __syncthreads();
    sum = 0.f; sq = 0.f;
#pragma unroll
    for (int i = 0; i < 8; ++i) { sum += s1[i]; sq += s2[i]; }
    const float mean = sum * (1.0f / DM);
    const float var  = sq * (1.0f / DM) - mean * mean;
    const float inv  = rsqrtf(var + 1e-5f);

    float4 gv = reinterpret_cast<const float4*>(go)[tid];
    float4 bv = reinterpret_cast<const float4*>(bo)[tid];
    float4 y;
    y.x = (v.x - mean) * inv * gv.x + bv.x;
    y.y = (v.y - mean) * inv * gv.y + bv.y;
    y.z = (v.z - mean) * inv * gv.z + bv.z;
    y.w = (v.w - mean) * inv * gv.w + bv.w;
    reinterpret_cast<float4*>(out + (size_t)r * DM)[tid] = y;
}

// ---------------- launch ---------------------------------------------------------
extern "C" void kernel_launch(void* const* d_in, const int* in_sizes, int n_in,
                              void* d_out, int out_size) {
    (void)in_sizes; (void)n_in; (void)out_size;
    const float* prev = (const float*)d_in[0];
    const float* toks = (const float*)d_in[1];
    const float* Wp   = (const float*)d_in[2];
    const float* bp   = (const float*)d_in[3];
    const float* gs   = (const float*)d_in[4];
    const float* bs   = (const float*)d_in[5];
    const float* gi   = (const float*)d_in[6];
    const float* bi   = (const float*)d_in[7];
    const float* go   = (const float*)d_in[8];
    const float* bo   = (const float*)d_in[9];
    const float* Wu   = (const float*)d_in[10];
    const float* bu   = (const float*)d_in[11];
    const float* Wr   = (const float*)d_in[12];
    const float* br   = (const float*)d_in[13];
    const float* Wn   = (const float*)d_in[14];
    const float* bn   = (const float*)d_in[15];
    float* out = (float*)d_out;

    __half *tok_h, *ps_h, *Wp_h, *Wp_l, *Wg_h, *Wg_l;
    __half *th, *tl, *ah, *ch, *c2h;
    cudaGetSymbolAddress((void**)&tok_h, g_tokens_h);
    cudaGetSymbolAddress((void**)&ps_h,  g_ps_h);
    cudaGetSymbolAddress((void**)&Wp_h,  g_Wp_h);
    cudaGetSymbolAddress((void**)&Wp_l,  g_Wp_l);
    cudaGetSymbolAddress((void**)&Wg_h,  g_Wg_h);
    cudaGetSymbolAddress((void**)&Wg_l,  g_Wg_l);
    cudaGetSymbolAddress((void**)&th,  g_tok_h);
    cudaGetSymbolAddress((void**)&tl,  g_tok_l);
    cudaGetSymbolAddress((void**)&ah,  g_attn_h);
    cudaGetSymbolAddress((void**)&ch,  g_cat_h);
    cudaGetSymbolAddress((void**)&c2h, g_cat2_h);

    // dynamic smem sizes (bytes)
    constexpr int SM_BIG    = (2*128*40 + 2*2*32*136) * 2;   // 55296  (128x128, BT=false)
    constexpr int SM_SCORES = (2*64*40  + 2*2*128*40) * 2;   // 51200  (64x128, BT=true)
    constexpr int SM_SMALL  = (2*64*40  + 2*2*32*136) * 2;   // 45056  (64x128, BT=false)
    cudaFuncSetAttribute((const void*)gemm2<128,128,64,32,false,0>,  cudaFuncAttributeMaxDynamicSharedMemorySize, SM_BIG);
    cudaFuncSetAttribute((const void*)gemm2<64,128,32,32,true,1>,    cudaFuncAttributeMaxDynamicSharedMemorySize, SM_SCORES);
    cudaFuncSetAttribute((const void*)gemm2<64,128,32,32,false,2>,   cudaFuncAttributeMaxDynamicSharedMemorySize, SM_SMALL);
    cudaFuncSetAttribute((const void*)gemm2<128,128,64,32,false,34>, cudaFuncAttributeMaxDynamicSharedMemorySize, SM_BIG);
    cudaFuncSetAttribute((const void*)gemm2<64,128,32,32,false,5>,   cudaFuncAttributeMaxDynamicSharedMemorySize, SM_SMALL);

    const long long WSTRIDE = (long long)2 * DM * DM;

    // 1) input conversions
    k_split_h<<<(B_*SQ*TK/4 + 255)/256, 256>>>(toks, tok_h, B_*SQ*TK/4);
    k_split_h<<<(B_*NS*DM/4 + 255)/256, 256>>>(prev, ps_h, B_*NS*DM/4);
    k_split2<<<(TK*DM/4 + 255)/256, 256>>>(Wp, Wp_h, Wp_l, TK*DM/4);
    k_split2w<<<dim3((2*DM*DM/4 + 255)/256, 3), 256>>>(Wu, Wr, Wn, Wg_h, Wg_l, 2*DM*DM/4);

    // 2) proj: tok = tokens @ W_proj + b   (M=32768,N=1024,K=768) NN
    gemm2<128,128,64,32,false,0><<<dim3(DM/128, (B_*SQ)/128, 1), 256, SM_BIG>>>(
        tok_h, Wp_h, Wp_l, TK, DM, TK, 0, 0, 0, bp, nullptr, nullptr);

    // 3) scores: ps @ tok^T (per batch, M=64,N=2048,K=1024) TN
    gemm2<64,128,32,32,true,1><<<dim3(SQ/128, 1, B_), 256, SM_SCORES>>>(
        ps_h, th, tl, DM, DM, DM,
        (long long)NS*DM, (long long)SQ*DM, NS, nullptr, nullptr, nullptr);

    // 4) softmax -> attn fp16
    k_softmax<<<B_*NS, 256>>>();

    // 5) routed: attn @ tok (per batch, M=64,N=1024,K=2048) NN
    gemm2<64,128,32,32,false,2><<<dim3(DM/128, 1, B_), 256, SM_SMALL>>>(
        ah, th, tl, SQ, DM, SQ,
        (long long)NS*SQ, (long long)SQ*DM, NS, nullptr, nullptr, nullptr);

    // 6) LN(prev), LN(routed) -> cat / cat2
    k_ln_cat<<<2*B_*NS, 256>>>(prev, gs, bs, gi, bi);

    // 7) gates u (z=0) and r (z=1) in ONE launch (M=1024,N=1024,K=2048) NN
    gemm2<128,128,64,32,false,34><<<dim3(DM/128, (B_*NS)/128, 2), 256, SM_BIG>>>(
        ch, Wg_h, Wg_l, 2*DM, DM, 2*DM, 0, WSTRIDE, 0, bu, br, nullptr);

    // 8) cand + gated combine (BM=64 -> 128 CTAs fills the chip)
    gemm2<64,128,32,32,false,5><<<dim3(DM/128, (B_*NS)/64, 1), 256, SM_SMALL>>>(
        c2h, Wg_h + 2*WSTRIDE, Wg_l + 2*WSTRIDE, 2*DM, DM, 2*DM, 0, 0, 0, bn, nullptr, prev);

    // 9) output LN
    k_ln_out<<<B_*NS, 256>>>(go, bo, out);
}

// round 6
// speedup vs baseline: 5.8478x; 1.5289x over previous
#include <cuda_runtime.h>
#include <cuda_fp16.h>
#include <stdint.h>

// Shapes (fixed)
#define B_  16
#define NS  64
#define SQ  2048
#define DM  1024
#define TK  768

// ---------------- scratch (device globals) ----------------------------------
__device__ __align__(16) __half g_tokens_h[(size_t)B_*SQ*TK];            // A of proj
__device__ __align__(16) __half g_Wp_h[TK*DM];                           // B of proj
__device__ __align__(16) __half g_Wg_h[3*(size_t)2*DM*DM];               // [Wu | Wr | Wn]
__device__ __align__(16) __half g_ps_h[B_*NS*DM];                        // A of scores
__device__ __align__(16) __half g_tok_h[(size_t)B_*SQ*DM];               // B of scores/routed
__device__ __align__(16) float g_scores[(size_t)B_*NS*SQ];
__device__ __align__(16) __half g_attn_h[B_*NS*SQ];                      // A of routed
__device__ __align__(16) float g_routed[B_*NS*DM];
__device__ __align__(16) __half g_cat_h[B_*NS*2*DM];                     // A of gates
__device__ __align__(16) __half g_cat2_h[B_*NS*2*DM];                    // A of cand
__device__ __align__(16) float g_u[B_*NS*DM];
__device__ __align__(16) float g_new[B_*NS*DM];

// ---------------- helpers ----------------------------------------------------
__device__ __forceinline__ unsigned s32(const void* p) {
    return (unsigned)__cvta_generic_to_shared(p);
}
__device__ __forceinline__ void cp16(unsigned dst, const void* src) {
    asm volatile("cp.async.cg.shared.global [%0], [%1], 16;\n" :: "r"(dst), "l"(src) : "memory");
}
__device__ __forceinline__ void cp_commit() { asm volatile("cp.async.commit_group;\n" ::); }
__device__ __forceinline__ void ldm_x4(uint32_t* r, unsigned a) {
    asm volatile("ldmatrix.sync.aligned.m8n8.x4.shared.b16 {%0,%1,%2,%3}, [%4];\n"
                 : "=r"(r[0]), "=r"(r[1]), "=r"(r[2]), "=r"(r[3]) : "r"(a));
}
__device__ __forceinline__ void ldm_x4_t(uint32_t* r, unsigned a) {
    asm volatile("ldmatrix.sync.aligned.m8n8.x4.trans.shared.b16 {%0,%1,%2,%3}, [%4];\n"
                 : "=r"(r[0]), "=r"(r[1]), "=r"(r[2]), "=r"(r[3]) : "r"(a));
}
__device__ __forceinline__ void mma16816(float* c, const uint32_t* a, const uint32_t* b) {
    asm volatile("mma.sync.aligned.m16n8k16.row.col.f32.f16.f16.f32 "
                 "{%0,%1,%2,%3}, {%4,%5,%6,%7}, {%8,%9}, {%0,%1,%2,%3};\n"
                 : "+f"(c[0]), "+f"(c[1]), "+f"(c[2]), "+f"(c[3])
                 : "r"(a[0]), "r"(a[1]), "r"(a[2]), "r"(a[3]), "r"(b[0]), "r"(b[1]));
}
__device__ __forceinline__ float warpSum(float v) {
#pragma unroll
    for (int o = 16; o; o >>= 1) v += __shfl_xor_sync(0xffffffffu, v, o);
    return v;
}
__device__ __forceinline__ float warpMax(float v) {
#pragma unroll
    for (int o = 16; o; o >>= 1) v = fmaxf(v, __shfl_xor_sync(0xffffffffu, v, o));
    return v;
}

// ---------------- fused vectorized epilogues ----------------------------------
// EPI: 0=tok(+bias) fp16  1=scores scale  2=routed  34=u/r gates (z picks)  5=cand
template<int EPI>
__device__ __forceinline__ void epi2(float a0, float a1, size_t gr, int c, int z,
                                     const float* __restrict__ bias,
                                     const float* __restrict__ aux) {
    if constexpr (EPI == 0) {
        size_t i = gr * DM + c;
        *reinterpret_cast<__half2*>(&g_tok_h[i]) =
            __half2(__float2half_rn(a0 + bias[c]), __float2half_rn(a1 + bias[c + 1]));
    } else if constexpr (EPI == 1) {
        *reinterpret_cast<float2*>(&g_scores[gr * SQ + c]) =
            make_float2(a0 * 0.03125f, a1 * 0.03125f);
    } else if constexpr (EPI == 2) {
        *reinterpret_cast<float2*>(&g_routed[gr * DM + c]) = make_float2(a0, a1);
    } else if constexpr (EPI == 34) {
        float s0 = 1.0f / (1.0f + expf(-(a0 + bias[c])));
        float s1 = 1.0f / (1.0f + expf(-(a1 + bias[c + 1])));
        if (z == 0) {
            *reinterpret_cast<float2*>(&g_u[gr * DM + c]) = make_float2(s0, s1);
        } else {
            size_t i = gr * (2 * DM) + c;
            __half2 ps = *reinterpret_cast<__half2*>(&g_cat_h[i]);
            *reinterpret_cast<__half2*>(&g_cat2_h[i]) =
                __half2(__float2half_rn(s0 * __half2float(ps.x)),
                        __float2half_rn(s1 * __half2float(ps.y)));
        }
    } else {
        size_t i = gr * DM + c;
        float2 u = *reinterpret_cast<const float2*>(&g_u[i]);
        float2 pv = *reinterpret_cast<const float2*>(&aux[i]);
        float t0 = tanhf(a0 + bias[c]), t1 = tanhf(a1 + bias[c + 1]);
        *reinterpret_cast<float2*>(&g_new[i]) =
            make_float2((1.0f - u.x) * pv.x + u.x * t0,
                        (1.0f - u.y) * pv.y + u.y * t1);
    }
}

// ---------------- single-pass fp16 tensor-core GEMM --------------------------
// A: M x K row-major fp16.
// BT=true : B stored N x K (K contiguous)  -> ldmatrix non-trans
// BT=false: B stored K x N (N contiguous)  -> ldmatrix .trans
// fp32 accum, fused epilogue EPI. BK=32, double buffered cp.async.
template<int BM, int BN, int WM, int WN, bool BT, int EPI>
__global__ __launch_bounds__(256, 2)
void gemm1(const __half* __restrict__ A, const __half* __restrict__ B,
           int lda, int ldb, int K,
           long long zA, long long zB, int rowz,
           const float* __restrict__ bias0, const float* __restrict__ bias1,
           const float* __restrict__ aux)
{
    constexpr int BK  = 32;
    constexpr int WMs = BM / WM;
    constexpr int MT  = WM / 16, NT = WN / 8;
    constexpr int AST = BK + 8;     // 40
    constexpr int BST = BK + 8;     // 40 (BT=true)
    constexpr int BNP = BN + 8;     // (BT=false)

    extern __shared__ __align__(16) __half sm[];
    __half* As = sm;                                    // [2][BM][AST]
    __half* Bs = sm + 2 * BM * AST;                     // BT: [2][BN][BST] else [2][BK][BNP]

    const int tid = threadIdx.x, lane = tid & 31, wid = tid >> 5;
    const int wm = wid % WMs, wn = wid / WMs;
    const int brow = blockIdx.y * BM, bcol = blockIdx.x * BN;
    const int z = blockIdx.z;

    const __half* Ap = A + (size_t)z * zA + (size_t)brow * lda;
    const __half* Bp = B + (size_t)z * zB;

    float acc[MT][NT][4];
#pragma unroll
    for (int i = 0; i < MT; ++i)
#pragma unroll
        for (int j = 0; j < NT; ++j)
#pragma unroll
            for (int e = 0; e < 4; ++e) acc[i][j][e] = 0.f;

    auto aOfs = [](int buf, int r, int c) -> int { return (buf * BM + r) * AST + c; };
    auto bOfs = [](int buf, int r, int c) -> int {
        return BT ? ((buf * BN + r) * BST + c) : ((buf * BK + r) * BNP + c);
    };

    auto loadSlab = [&](int buf, int k0) {
        for (int i = tid; i < BM * 4; i += 256) {
            int r = i >> 2, c = (i & 3) * 8;
            cp16(s32(&As[aOfs(buf, r, c)]), Ap + (size_t)r * lda + k0 + c);
        }
        if (BT) {
            for (int i = tid; i < BN * 4; i += 256) {
                int n = i >> 2, c = (i & 3) * 8;
                cp16(s32(&Bs[bOfs(buf, n, c)]), Bp + (size_t)(bcol + n) * ldb + k0 + c);
            }
        } else {
            constexpr int CH = BK * BN / 8;
            for (int i = tid; i < CH; i += 256) {
                int k = i / (BN / 8); int n8 = (i % (BN / 8)) * 8;
                cp16(s32(&Bs[bOfs(buf, k, n8)]), Bp + (size_t)(k0 + k) * ldb + bcol + n8);
            }
        }
        cp_commit();
    };

    const int nk = K / BK;
    loadSlab(0, 0);

    for (int ks = 0; ks < nk; ++ks) {
        const int buf = ks & 1;
        if (ks + 1 < nk) {
            loadSlab(buf ^ 1, (ks + 1) * BK);
            asm volatile("cp.async.wait_group 1;\n" ::);
        } else {
            asm volatile("cp.async.wait_group 0;\n" ::);
        }
        __syncthreads();

#pragma unroll
        for (int kk2 = 0; kk2 < 2; ++kk2) {
            uint32_t af[MT][4];
#pragma unroll
            for (int mt = 0; mt < MT; ++mt) {
                int row = wm * WM + mt * 16 + (lane & 15);
                int col = kk2 * 16 + (lane >> 4) * 8;
                ldm_x4(af[mt], s32(&As[aOfs(buf, row, col)]));
            }
            uint32_t bf[NT][2];
#pragma unroll
            for (int p = 0; p < NT / 2; ++p) {
                int nbase = wn * WN + p * 16;
                uint32_t t[4];
                if (BT) {
                    int r = nbase + (lane & 7) + ((lane >> 4) << 3);
                    int c = kk2 * 16 + ((lane >> 3) & 1) * 8;
                    ldm_x4(t, s32(&Bs[bOfs(buf, r, c)]));
                } else {
                    int k = kk2 * 16 + (lane & 15);
                    int nc = nbase + ((lane >> 4) << 3);
                    ldm_x4_t(t, s32(&Bs[bOfs(buf, k, nc)]));
                }
                bf[2*p][0]=t[0]; bf[2*p][1]=t[1]; bf[2*p+1][0]=t[2]; bf[2*p+1][1]=t[3];
            }
#pragma unroll
            for (int mt = 0; mt < MT; ++mt)
#pragma unroll
                for (int nt = 0; nt < NT; ++nt)
                    mma16816(acc[mt][nt], af[mt], bf[nt]);
        }
        __syncthreads();
    }

    // epilogue (vectorized pairs)
    const float* bias = (z != 0 && bias1) ? bias1 : bias0;
#pragma unroll
    for (int mt = 0; mt < MT; ++mt) {
        int r0 = brow + wm * WM + mt * 16 + (lane >> 2);
#pragma unroll
        for (int nt = 0; nt < NT; ++nt) {
            int c0 = bcol + wn * WN + nt * 8 + ((lane & 3) << 1);
            size_t g0 = (size_t)z * rowz + r0;
            epi2<EPI>(acc[mt][nt][0], acc[mt][nt][1], g0,     c0, z, bias, aux);
            epi2<EPI>(acc[mt][nt][2], acc[mt][nt][3], g0 + 8, c0, z, bias, aux);
        }
    }
}

// ---------------- fp32 -> fp16 --------------------------------------------------
__global__ __launch_bounds__(256) void k_split_h(const float* __restrict__ src,
                                                 __half* __restrict__ h, int n4) {
    int i = blockIdx.x * blockDim.x + threadIdx.x;
    if (i >= n4) return;
    float4 v = reinterpret_cast<const float4*>(src)[i];
    reinterpret_cast<__half2*>(h)[2*i]   = __half2(__float2half_rn(v.x), __float2half_rn(v.y));
    reinterpret_cast<__half2*>(h)[2*i+1] = __half2(__float2half_rn(v.z), __float2half_rn(v.w));
}

// ---------------- 3 weights -> contiguous fp16 ----------------------------------
__global__ __launch_bounds__(256) void k_split_w(const float* __restrict__ w0,
                                                 const float* __restrict__ w1,
                                                 const float* __restrict__ w2,
                                                 __half* __restrict__ h, int n4) {
    int i = blockIdx.x * blockDim.x + threadIdx.x;
    if (i >= n4) return;
    int z = blockIdx.y;
    const float* src = (z == 0) ? w0 : (z == 1) ? w1 : w2;
    size_t o = (size_t)z * n4 + i;
    float4 v = reinterpret_cast<const float4*>(src)[i];
    reinterpret_cast<__half2*>(h)[2*o]   = __half2(__float2half_rn(v.x), __float2half_rn(v.y));
    reinterpret_cast<__half2*>(h)[2*o+1] = __half2(__float2half_rn(v.z), __float2half_rn(v.w));
}

// ---------------- softmax over S (2048) -> attn fp16 ---------------------------
__global__ __launch_bounds__(256) void k_softmax() {
    const size_t row = blockIdx.x;
    float* x = g_scores + row * SQ;
    const int tid = threadIdx.x;
    __shared__ float red[8], red2[8];

    float4 v0 = reinterpret_cast<float4*>(x)[tid];
    float4 v1 = reinterpret_cast<float4*>(x)[tid + 256];
    float m = fmaxf(fmaxf(fmaxf(v0.x, v0.y), fmaxf(v0.z, v0.w)),
                    fmaxf(fmaxf(v1.x, v1.y), fmaxf(v1.z, v1.w)));
    m = warpMax(m);
    if ((tid & 31) == 0) red[tid >> 5] = m;
    __syncthreads();
    m = red[0];
#pragma unroll
    for (int i = 1; i < 8; ++i) m = fmaxf(m, red[i]);

    v0.x = expf(v0.x - m); v0.y = expf(v0.y - m); v0.z = expf(v0.z - m); v0.w = expf(v0.w - m);
    v1.x = expf(v1.x - m); v1.y = expf(v1.y - m); v1.z = expf(v1.z - m); v1.w = expf(v1.w - m);
    float s = v0.x + v0.y + v0.z + v0.w + v1.x + v1.y + v1.z + v1.w;
    s = warpSum(s);
    if ((tid & 31) == 0) red2[tid >> 5] = s;
    __syncthreads();
    s = 0.f;
#pragma unroll
    for (int i = 0; i < 8; ++i) s += red2[i];
    const float inv = 1.0f / s;

    size_t b0 = row * SQ + (size_t)tid * 4;
    size_t b1 = b0 + 1024;
    *reinterpret_cast<__half2*>(&g_attn_h[b0]) =
        __half2(__float2half_rn(v0.x*inv), __float2half_rn(v0.y*inv));
    *reinterpret_cast<__half2*>(&g_attn_h[b0+2]) =
        __half2(__float2half_rn(v0.z*inv), __float2half_rn(v0.w*inv));
    *reinterpret_cast<__half2*>(&g_attn_h[b1]) =
        __half2(__float2half_rn(v1.x*inv), __float2half_rn(v1.y*inv));
    *reinterpret_cast<__half2*>(&g_attn_h[b1+2]) =
        __half2(__float2half_rn(v1.z*inv), __float2half_rn(v1.w*inv));
}

// ---------------- two LayerNorms -> cat / cat2 (fp16) --------------------------
__global__ __launch_bounds__(256) void k_ln_cat(const float* __restrict__ PS,
                                                const float* __restrict__ gs,
                                                const float* __restrict__ bs,
                                                const float* __restrict__ gi,
                                                const float* __restrict__ bi) {
    const int rowId = blockIdx.x;
    const bool isInput = rowId >= B_ * NS;
    const int r = isInput ? rowId - B_ * NS : rowId;
    const float* x = isInput ? (g_routed + (size_t)r * DM) : (PS + (size_t)r * DM);
    const float* gamma = isInput ? gi : gs;
    const float* beta  = isInput ? bi : bs;
    const int tid = threadIdx.x;
    __shared__ float s1[8], s2[8];

    float4 v = reinterpret_cast<const float4*>(x)[tid];
    float sum = v.x + v.y + v.z + v.w;
    float sq  = v.x*v.x + v.y*v.y + v.z*v.z + v.w*v.w;
    sum = warpSum(sum); sq = warpSum(sq);
    if ((tid & 31) == 0) { s1[tid >> 5] = sum; s2[tid >> 5] = sq; }
    __syncthreads();
    sum = 0.f; sq = 0.f;
#pragma unroll
    for (int i = 0; i < 8; ++i) { sum += s1[i]; sq += s2[i]; }
    const float mean = sum * (1.0f / DM);
    const float var  = sq * (1.0f / DM) - mean * mean;
    const float inv  = rsqrtf(var + 1e-5f);

    float4 gv = reinterpret_cast<const float4*>(gamma)[tid];
    float4 bv = reinterpret_cast<const float4*>(beta)[tid];
    __half h0 = __float2half_rn((v.x - mean) * inv * gv.x + bv.x);
    __half h1 = __float2half_rn((v.y - mean) * inv * gv.y + bv.y);
    __half h2 = __float2half_rn((v.z - mean) * inv * gv.z + bv.z);
    __half h3 = __float2half_rn((v.w - mean) * inv * gv.w + bv.w);

    const size_t off = (size_t)r * (2 * DM) + (isInput ? DM : 0) + (size_t)tid * 4;
    *reinterpret_cast<__half2*>(&g_cat_h[off])     = __half2(h0, h1);
    *reinterpret_cast<__half2*>(&g_cat_h[off + 2]) = __half2(h2, h3);
    if (isInput) {
        *reinterpret_cast<__half2*>(&g_cat2_h[off])     = __half2(h0, h1);
        *reinterpret_cast<__half2*>(&g_cat2_h[off + 2]) = __half2(h2, h3);
    }
}

// ---------------- output LayerNorm ---------------------------------------------
__global__ __launch_bounds__(256) void k_ln_out(const float* __restrict__ go,
                                                const float* __restrict__ bo,
                                                float* __restrict__ out) {
    const int r = blockIdx.x;
    const float* x = g_new + (size_t)r * DM;
    const int tid = threadIdx.x;
    __shared__ float s1[8], s2[8];

    float4 v = reinterpret_cast<const float4*>(x)[tid];
    float sum = v.x + v.y + v.z + v.w;
    float sq  = v.x*v.x + v.y*v.y + v.z*v.z + v.w*v.w;
    sum = warpSum(sum); sq = warpSum(sq);
    if ((tid & 31) == 0) { s1[tid >> 5] = sum; s2[tid >> 5] = sq; }
    __syncthreads();
    sum = 0.f; sq = 0.f;
#pragma unroll
    for (int i = 0; i < 8; ++i) { sum += s1[i]; sq += s2[i]; }
    const float mean = sum * (1.0f / DM);
    const float var  = sq * (1.0f / DM) - mean * mean;
    const float inv  = rsqrtf(var + 1e-5f);

    float4 gv = reinterpret_cast<const float4*>(go)[tid];
    float4 bv = reinterpret_cast<const float4*>(bo)[tid];
    float4 y;
    y.x = (v.x - mean) * inv * gv.x + bv.x;
    y.y = (v.y - mean) * inv * gv.y + bv.y;
    y.z = (v.z - mean) * inv * gv.z + bv.z;
    y.w = (v.w - mean) * inv * gv.w + bv.w;
    reinterpret_cast<float4*>(out + (size_t)r * DM)[tid] = y;
}

// ---------------- launch ---------------------------------------------------------
extern "C" void kernel_launch(void* const* d_in, const int* in_sizes, int n_in,
                              void* d_out, int out_size) {
    (void)in_sizes; (void)n_in; (void)out_size;
    const float* prev = (const float*)d_in[0];
    const float* toks = (const float*)d_in[1];
    const float* Wp   = (const float*)d_in[2];
    const float* bp   = (const float*)d_in[3];
    const float* gs   = (const float*)d_in[4];
    const float* bs   = (const float*)d_in[5];
    const float* gi   = (const float*)d_in[6];
    const float* bi   = (const float*)d_in[7];
    const float* go   = (const float*)d_in[8];
    const float* bo   = (const float*)d_in[9];
    const float* Wu   = (const float*)d_in[10];
    const float* bu   = (const float*)d_in[11];
    const float* Wr   = (const float*)d_in[12];
    const float* br   = (const float*)d_in[13];
    const float* Wn   = (const float*)d_in[14];
    const float* bn   = (const float*)d_in[15];
    float* out = (float*)d_out;

    __half *tok_h, *ps_h, *Wp_h, *Wg_h, *th, *ah, *ch, *c2h;
    cudaGetSymbolAddress((void**)&tok_h, g_tokens_h);
    cudaGetSymbolAddress((void**)&ps_h,  g_ps_h);
    cudaGetSymbolAddress((void**)&Wp_h,  g_Wp_h);
    cudaGetSymbolAddress((void**)&Wg_h,  g_Wg_h);
    cudaGetSymbolAddress((void**)&th,  g_tok_h);
    cudaGetSymbolAddress((void**)&ah,  g_attn_h);
    cudaGetSymbolAddress((void**)&ch,  g_cat_h);
    cudaGetSymbolAddress((void**)&c2h, g_cat2_h);

    // dynamic smem sizes (bytes)
    constexpr int SM_BIG    = (2*128*40 + 2*32*136) * 2;   // 29184 (128x128, BT=false)
    constexpr int SM_SCORES = (2*64*40  + 2*128*40) * 2;   // 30720 (64x128, BT=true)
    constexpr int SM_SMALL  = (2*64*40  + 2*32*136) * 2;   // 18944 (64x128, BT=false)
    cudaFuncSetAttribute((const void*)gemm1<128,128,64,32,false,0>,  cudaFuncAttributeMaxDynamicSharedMemorySize, SM_BIG);
    cudaFuncSetAttribute((const void*)gemm1<64,128,32,32,true,1>,    cudaFuncAttributeMaxDynamicSharedMemorySize, SM_SCORES);
    cudaFuncSetAttribute((const void*)gemm1<64,128,32,32,false,2>,   cudaFuncAttributeMaxDynamicSharedMemorySize, SM_SMALL);
    cudaFuncSetAttribute((const void*)gemm1<128,128,64,32,false,34>, cudaFuncAttributeMaxDynamicSharedMemorySize, SM_BIG);
    cudaFuncSetAttribute((const void*)gemm1<64,128,32,32,false,5>,   cudaFuncAttributeMaxDynamicSharedMemorySize, SM_SMALL);

    const long long WSTRIDE = (long long)2 * DM * DM;

    // 1) input conversions
    k_split_h<<<(B_*SQ*TK/4 + 255)/256, 256>>>(toks, tok_h, B_*SQ*TK/4);
    k_split_h<<<(B_*NS*DM/4 + 255)/256, 256>>>(prev, ps_h, B_*NS*DM/4);
    k_split_h<<<(TK*DM/4 + 255)/256, 256>>>(Wp, Wp_h, TK*DM/4);
    k_split_w<<<dim3((2*DM*DM/4 + 255)/256, 3), 256>>>(Wu, Wr, Wn, Wg_h, 2*DM*DM/4);

    // 2) proj: tok = tokens @ W_proj + b   (M=32768,N=1024,K=768) NN
    gemm1<128,128,64,32,false,0><<<dim3(DM/128, (B_*SQ)/128, 1), 256, SM_BIG>>>(
        tok_h, Wp_h, TK, DM, TK, 0, 0, 0, bp, nullptr, nullptr);

    // 3) scores: ps @ tok^T (per batch, M=64,N=2048,K=1024) TN
    gemm1<64,128,32,32,true,1><<<dim3(SQ/128, 1, B_), 256, SM_SCORES>>>(
        ps_h, th, DM, DM, DM,
        (long long)NS*DM, (long long)SQ*DM, NS, nullptr, nullptr, nullptr);

    // 4) softmax -> attn fp16
    k_softmax<<<B_*NS, 256>>>();

    // 5) routed: attn @ tok (per batch, M=64,N=1024,K=2048) NN
    gemm1<64,128,32,32,false,2><<<dim3(DM/128, 1, B_), 256, SM_SMALL>>>(
        ah, th, SQ, DM, SQ,
        (long long)NS*SQ, (long long)SQ*DM, NS, nullptr, nullptr, nullptr);

    // 6) LN(prev), LN(routed) -> cat / cat2
    k_ln_cat<<<2*B_*NS, 256>>>(prev, gs, bs, gi, bi);

    // 7) gates u (z=0) and r (z=1) in ONE launch (M=1024,N=1024,K=2048) NN
    gemm1<128,128,64,32,false,34><<<dim3(DM/128, (B_*NS)/128, 2), 256, SM_BIG>>>(
        ch, Wg_h, 2*DM, DM, 2*DM, 0, WSTRIDE, 0, bu, br, nullptr);

    // 8) cand + gated combine (BM=64 -> 128 CTAs fills the chip)
    gemm1<64,128,32,32,false,5><<<dim3(DM/128, (B_*NS)/64, 1), 256, SM_SMALL>>>(
        c2h, Wg_h + 2*WSTRIDE, 2*DM, DM, 2*DM, 0, 0, 0, bn, nullptr, prev);

    // 9) output LN
    k_ln_out<<<B_*NS, 256>>>(go, bo, out);
}

// round 7
// speedup vs baseline: 6.3562x; 1.0870x over previous
#include <cuda_runtime.h>
#include <cuda_fp16.h>
#include <stdint.h>

// Shapes (fixed)
#define B_  16
#define NS  64
#define SQ  2048
#define DM  1024
#define TK  768

// ---------------- scratch (device globals) ----------------------------------
__device__ __align__(16) __half g_tokens_h[(size_t)B_*SQ*TK];            // A of proj
__device__ __align__(16) __half g_Wp_h[TK*DM];                           // B of proj
__device__ __align__(16) __half g_Wg_h[3*(size_t)2*DM*DM];               // [Wu | Wr | Wn]
__device__ __align__(16) __half g_ps_h[B_*NS*DM];                        // A of scores
__device__ __align__(16) __half g_tok_h[(size_t)B_*SQ*DM];               // B of scores/routed
__device__ __align__(16) float g_scores[(size_t)B_*NS*SQ];
__device__ __align__(16) __half g_attn_h[B_*NS*SQ];                      // A of routed
__device__ __align__(16) float g_routed[B_*NS*DM];
__device__ __align__(16) __half g_cat_h[B_*NS*2*DM];                     // A of gates
__device__ __align__(16) __half g_cat2_h[B_*NS*2*DM];                    // A of cand
__device__ __align__(16) float g_u[B_*NS*DM];
__device__ __align__(16) float g_new[B_*NS*DM];

// ---------------- helpers ----------------------------------------------------
__device__ __forceinline__ unsigned s32(const void* p) {
    return (unsigned)__cvta_generic_to_shared(p);
}
__device__ __forceinline__ void cp16(unsigned dst, const void* src) {
    asm volatile("cp.async.cg.shared.global [%0], [%1], 16;\n" :: "r"(dst), "l"(src) : "memory");
}
__device__ __forceinline__ void cp_commit() { asm volatile("cp.async.commit_group;\n" ::); }
__device__ __forceinline__ void ldm_x4(uint32_t* r, unsigned a) {
    asm volatile("ldmatrix.sync.aligned.m8n8.x4.shared.b16 {%0,%1,%2,%3}, [%4];\n"
                 : "=r"(r[0]), "=r"(r[1]), "=r"(r[2]), "=r"(r[3]) : "r"(a));
}
__device__ __forceinline__ void ldm_x4_t(uint32_t* r, unsigned a) {
    asm volatile("ldmatrix.sync.aligned.m8n8.x4.trans.shared.b16 {%0,%1,%2,%3}, [%4];\n"
                 : "=r"(r[0]), "=r"(r[1]), "=r"(r[2]), "=r"(r[3]) : "r"(a));
}
__device__ __forceinline__ void mma16816(float* c, const uint32_t* a, const uint32_t* b) {
    asm volatile("mma.sync.aligned.m16n8k16.row.col.f32.f16.f16.f32 "
                 "{%0,%1,%2,%3}, {%4,%5,%6,%7}, {%8,%9}, {%0,%1,%2,%3};\n"
                 : "+f"(c[0]), "+f"(c[1]), "+f"(c[2]), "+f"(c[3])
                 : "r"(a[0]), "r"(a[1]), "r"(a[2]), "r"(a[3]), "r"(b[0]), "r"(b[1]));
}
__device__ __forceinline__ float warpSum(float v) {
#pragma unroll
    for (int o = 16; o; o >>= 1) v += __shfl_xor_sync(0xffffffffu, v, o);
    return v;
}
__device__ __forceinline__ float warpMax(float v) {
#pragma unroll
    for (int o = 16; o; o >>= 1) v = fmaxf(v, __shfl_xor_sync(0xffffffffu, v, o));
    return v;
}

// ---------------- fused vectorized epilogues ----------------------------------
// EPI: 0=tok(+bias) fp16  1=scores scale  2=routed  34=u/r gates (z picks)  5=cand
template<int EPI>
__device__ __forceinline__ void epi2(float a0, float a1, size_t gr, int c, int z,
                                     const float* __restrict__ bias,
                                     const float* __restrict__ aux) {
    if constexpr (EPI == 0) {
        size_t i = gr * DM + c;
        *reinterpret_cast<__half2*>(&g_tok_h[i]) =
            __half2(__float2half_rn(a0 + bias[c]), __float2half_rn(a1 + bias[c + 1]));
    } else if constexpr (EPI == 1) {
        *reinterpret_cast<float2*>(&g_scores[gr * SQ + c]) =
            make_float2(a0 * 0.03125f, a1 * 0.03125f);
    } else if constexpr (EPI == 2) {
        *reinterpret_cast<float2*>(&g_routed[gr * DM + c]) = make_float2(a0, a1);
    } else if constexpr (EPI == 34) {
        float s0 = 1.0f / (1.0f + expf(-(a0 + bias[c])));
        float s1 = 1.0f / (1.0f + expf(-(a1 + bias[c + 1])));
        if (z == 0) {
            *reinterpret_cast<float2*>(&g_u[gr * DM + c]) = make_float2(s0, s1);
        } else {
            size_t i = gr * (2 * DM) + c;
            __half2 ps = *reinterpret_cast<__half2*>(&g_cat_h[i]);
            *reinterpret_cast<__half2*>(&g_cat2_h[i]) =
                __half2(__float2half_rn(s0 * __half2float(ps.x)),
                        __float2half_rn(s1 * __half2float(ps.y)));
        }
    } else {
        size_t i = gr * DM + c;
        float2 u = *reinterpret_cast<const float2*>(&g_u[i]);
        float2 pv = *reinterpret_cast<const float2*>(&aux[i]);
        float t0 = tanhf(a0 + bias[c]), t1 = tanhf(a1 + bias[c + 1]);
        *reinterpret_cast<float2*>(&g_new[i]) =
            make_float2((1.0f - u.x) * pv.x + u.x * t0,
                        (1.0f - u.y) * pv.y + u.y * t1);
    }
}

// ---------------- single-pass fp16 GEMM, 3-stage cp.async pipeline ------------
// A: M x K row-major fp16.
// BT=true : B stored N x K (K contiguous)  -> ldmatrix non-trans
// BT=false: B stored K x N (N contiguous)  -> ldmatrix .trans
// fp32 accum, fused epilogue EPI. BK=32, ONE __syncthreads per K-iter.
template<int BM, int BN, int WM, int WN, bool BT, int EPI>
__global__ __launch_bounds__(256, 2)
void gemm1(const __half* __restrict__ A, const __half* __restrict__ B,
           int lda, int ldb, int K,
           long long zA, long long zB, int rowz,
           const float* __restrict__ bias0, const float* __restrict__ bias1,
           const float* __restrict__ aux)
{
    constexpr int BK  = 32;
    constexpr int WMs = BM / WM;
    constexpr int MT  = WM / 16, NT = WN / 8;
    constexpr int AST = BK + 8;     // 40
    constexpr int BST = BK + 8;     // 40 (BT=true)
    constexpr int BNP = BN + 8;     // (BT=false)

    extern __shared__ __align__(16) __half sm[];
    __half* As = sm;                                    // [3][BM][AST]
    __half* Bs = sm + 3 * BM * AST;                     // BT: [3][BN][BST] else [3][BK][BNP]

    const int tid = threadIdx.x, lane = tid & 31, wid = tid >> 5;
    const int wm = wid % WMs, wn = wid / WMs;
    const int brow = blockIdx.y * BM, bcol = blockIdx.x * BN;
    const int z = blockIdx.z;

    const __half* Ap = A + (size_t)z * zA + (size_t)brow * lda;
    const __half* Bp = B + (size_t)z * zB;

    float acc[MT][NT][4];
#pragma unroll
    for (int i = 0; i < MT; ++i)
#pragma unroll
        for (int j = 0; j < NT; ++j)
#pragma unroll
            for (int e = 0; e < 4; ++e) acc[i][j][e] = 0.f;

    auto aOfs = [](int buf, int r, int c) -> int { return (buf * BM + r) * AST + c; };
    auto bOfs = [](int buf, int r, int c) -> int {
        return BT ? ((buf * BN + r) * BST + c) : ((buf * BK + r) * BNP + c);
    };

    auto loadSlab = [&](int buf, int k0) {
        for (int i = tid; i < BM * 4; i += 256) {
            int r = i >> 2, c = (i & 3) * 8;
            cp16(s32(&As[aOfs(buf, r, c)]), Ap + (size_t)r * lda + k0 + c);
        }
        if (BT) {
            for (int i = tid; i < BN * 4; i += 256) {
                int n = i >> 2, c = (i & 3) * 8;
                cp16(s32(&Bs[bOfs(buf, n, c)]), Bp + (size_t)(bcol + n) * ldb + k0 + c);
            }
        } else {
            constexpr int CH = BK * BN / 8;
            for (int i = tid; i < CH; i += 256) {
                int k = i / (BN / 8); int n8 = (i % (BN / 8)) * 8;
                cp16(s32(&Bs[bOfs(buf, k, n8)]), Bp + (size_t)(k0 + k) * ldb + bcol + n8);
            }
        }
        cp_commit();
    };

    const int nk = K / BK;
    loadSlab(0, 0);
    if (nk > 1) loadSlab(1, BK);

    int buf = 0;
    for (int ks = 0; ks < nk; ++ks) {
        if (ks + 1 < nk) {
            asm volatile("cp.async.wait_group 1;\n" ::);
        } else {
            asm volatile("cp.async.wait_group 0;\n" ::);
        }
        __syncthreads();
        if (ks + 2 < nk) {
            int nb = buf + 2; if (nb >= 3) nb -= 3;
            loadSlab(nb, (ks + 2) * BK);
        }

#pragma unroll
        for (int kk2 = 0; kk2 < 2; ++kk2) {
            uint32_t af[MT][4];
#pragma unroll
            for (int mt = 0; mt < MT; ++mt) {
                int row = wm * WM + mt * 16 + (lane & 15);
                int col = kk2 * 16 + (lane >> 4) * 8;
                ldm_x4(af[mt], s32(&As[aOfs(buf, row, col)]));
            }
            uint32_t bf[NT][2];
#pragma unroll
            for (int p = 0; p < NT / 2; ++p) {
                int nbase = wn * WN + p * 16;
                uint32_t t[4];
                if (BT) {
                    int r = nbase + (lane & 7) + ((lane >> 4) << 3);
                    int c = kk2 * 16 + ((lane >> 3) & 1) * 8;
                    ldm_x4(t, s32(&Bs[bOfs(buf, r, c)]));
                } else {
                    int k = kk2 * 16 + (lane & 15);
                    int nc = nbase + ((lane >> 4) << 3);
                    ldm_x4_t(t, s32(&Bs[bOfs(buf, k, nc)]));
                }
                bf[2*p][0]=t[0]; bf[2*p][1]=t[1]; bf[2*p+1][0]=t[2]; bf[2*p+1][1]=t[3];
            }
#pragma unroll
            for (int mt = 0; mt < MT; ++mt)
#pragma unroll
                for (int nt = 0; nt < NT; ++nt)
                    mma16816(acc[mt][nt], af[mt], bf[nt]);
        }
        if (++buf == 3) buf = 0;
    }

    // epilogue (vectorized pairs)
    const float* bias = (z != 0 && bias1) ? bias1 : bias0;
#pragma unroll
    for (int mt = 0; mt < MT; ++mt) {
        int r0 = brow + wm * WM + mt * 16 + (lane >> 2);
#pragma unroll
        for (int nt = 0; nt < NT; ++nt) {
            int c0 = bcol + wn * WN + nt * 8 + ((lane & 3) << 1);
            size_t g0 = (size_t)z * rowz + r0;
            epi2<EPI>(acc[mt][nt][0], acc[mt][nt][1], g0,     c0, z, bias, aux);
            epi2<EPI>(acc[mt][nt][2], acc[mt][nt][3], g0 + 8, c0, z, bias, aux);
        }
    }
}

// ---------------- unified fp32 -> fp16 conversion (one launch) -----------------
// Segments (in 256-float4 blocks): tokens | prev | Wp | Wu | Wr | Wn
#define NB_TOK (B_*SQ*TK/4/256)     // 24576
#define NB_PS  (B_*NS*DM/4/256)     // 1024
#define NB_WP  (TK*DM/4/256)        // 768
#define NB_WG  (2*DM*DM/4/256)      // 2048 per gate weight
__global__ __launch_bounds__(256) void k_convert(const float* __restrict__ toks,
                                                 const float* __restrict__ prev,
                                                 const float* __restrict__ Wp,
                                                 const float* __restrict__ Wu,
                                                 const float* __restrict__ Wr,
                                                 const float* __restrict__ Wn,
                                                 __half* __restrict__ tok_h,
                                                 __half* __restrict__ ps_h,
                                                 __half* __restrict__ Wp_h,
                                                 __half* __restrict__ Wg_h) {
    int b = blockIdx.x;
    const float* src; __half* dst; int i;
    if (b < NB_TOK) { src = toks; dst = tok_h; i = b; }
    else if ((b -= NB_TOK) < NB_PS) { src = prev; dst = ps_h; i = b; }
    else if ((b -= NB_PS) < NB_WP)  { src = Wp;   dst = Wp_h; i = b; }
    else if ((b -= NB_WP) < NB_WG)  { src = Wu;   dst = Wg_h; i = b; }
    else if ((b -= NB_WG) < NB_WG)  { src = Wr;   dst = Wg_h + (size_t)2*DM*DM; i = b; }
    else { b -= NB_WG; src = Wn; dst = Wg_h + (size_t)4*DM*DM; i = b; }
    size_t idx = (size_t)i * 256 + threadIdx.x;
    float4 v = reinterpret_cast<const float4*>(src)[idx];
    reinterpret_cast<__half2*>(dst)[2*idx]   = __half2(__float2half_rn(v.x), __float2half_rn(v.y));
    reinterpret_cast<__half2*>(dst)[2*idx+1] = __half2(__float2half_rn(v.z), __float2half_rn(v.w));
}

// ---------------- softmax over S (2048) -> attn fp16 ---------------------------
__global__ __launch_bounds__(256) void k_softmax() {
    const size_t row = blockIdx.x;
    float* x = g_scores + row * SQ;
    const int tid = threadIdx.x;
    __shared__ float red[8], red2[8];

    float4 v0 = reinterpret_cast<float4*>(x)[tid];
    float4 v1 = reinterpret_cast<float4*>(x)[tid + 256];
    float m = fmaxf(fmaxf(fmaxf(v0.x, v0.y), fmaxf(v0.z, v0.w)),
                    fmaxf(fmaxf(v1.x, v1.y), fmaxf(v1.z, v1.w)));
    m = warpMax(m);
    if ((tid & 31) == 0) red[tid >> 5] = m;
    __syncthreads();
    m = red[0];
#pragma unroll
    for (int i = 1; i < 8; ++i) m = fmaxf(m, red[i]);

    v0.x = expf(v0.x - m); v0.y = expf(v0.y - m); v0.z = expf(v0.z - m); v0.w = expf(v0.w - m);
    v1.x = expf(v1.x - m); v1.y = expf(v1.y - m); v1.z = expf(v1.z - m); v1.w = expf(v1.w - m);
    float s = v0.x + v0.y + v0.z + v0.w + v1.x + v1.y + v1.z + v1.w;
    s = warpSum(s);
    if ((tid & 31) == 0) red2[tid >> 5] = s;
    __syncthreads();
    s = 0.f;
#pragma unroll
    for (int i = 0; i < 8; ++i) s += red2[i];
    const float inv = 1.0f / s;

    size_t b0 = row * SQ + (size_t)tid * 4;
    size_t b1 = b0 + 1024;
    *reinterpret_cast<__half2*>(&g_attn_h[b0]) =
        __half2(__float2half_rn(v0.x*inv), __float2half_rn(v0.y*inv));
    *reinterpret_cast<__half2*>(&g_attn_h[b0+2]) =
        __half2(__float2half_rn(v0.z*inv), __float2half_rn(v0.w*inv));
    *reinterpret_cast<__half2*>(&g_attn_h[b1]) =
        __half2(__float2half_rn(v1.x*inv), __float2half_rn(v1.y*inv));
    *reinterpret_cast<__half2*>(&g_attn_h[b1+2]) =
        __half2(__float2half_rn(v1.z*inv), __float2half_rn(v1.w*inv));
}

// ---------------- two LayerNorms -> cat / cat2 (fp16) --------------------------
__global__ __launch_bounds__(256) void k_ln_cat(const float* __restrict__ PS,
                                                const float* __restrict__ gs,
                                                const float* __restrict__ bs,
                                                const float* __restrict__ gi,
                                                const float* __restrict__ bi) {
    const int rowId = blockIdx.x;
    const bool isInput = rowId >= B_ * NS;
    const int r = isInput ? rowId - B_ * NS : rowId;
    const float* x = isInput ? (g_routed + (size_t)r * DM) : (PS + (size_t)r * DM);
    const float* gamma = isInput ? gi : gs;
    const float* beta  = isInput ? bi : bs;
    const int tid = threadIdx.x;
    __shared__ float s1[8], s2[8];

    float4 v = reinterpret_cast<const float4*>(x)[tid];
    float sum = v.x + v.y + v.z + v.w;
    float sq  = v.x*v.x + v.y*v.y + v.z*v.z + v.w*v.w;
    sum = warpSum(sum); sq = warpSum(sq);
    if ((tid & 31) == 0) { s1[tid >> 5] = sum; s2[tid >> 5] = sq; }
    __syncthreads();
    sum = 0.f; sq = 0.f;
#pragma unroll
    for (int i = 0; i < 8; ++i) { sum += s1[i]; sq += s2[i]; }
    const float mean = sum * (1.0f / DM);
    const float var  = sq * (1.0f / DM) - mean * mean;
    const float inv  = rsqrtf(var + 1e-5f);

    float4 gv = reinterpret_cast<const float4*>(gamma)[tid];
    float4 bv = reinterpret_cast<const float4*>(beta)[tid];
    __half h0 = __float2half_rn((v.x - mean) * inv * gv.x + bv.x);
    __half h1 = __float2half_rn((v.y - mean) * inv * gv.y + bv.y);
    __half h2 = __float2half_rn((v.z - mean) * inv * gv.z + bv.z);
    __half h3 = __float2half_rn((v.w - mean) * inv * gv.w + bv.w);

    const size_t off = (size_t)r * (2 * DM) + (isInput ? DM : 0) + (size_t)tid * 4;
    *reinterpret_cast<__half2*>(&g_cat_h[off])     = __half2(h0, h1);
    *reinterpret_cast<__half2*>(&g_cat_h[off + 2]) = __half2(h2, h3);
    if (isInput) {
        *reinterpret_cast<__half2*>(&g_cat2_h[off])     = __half2(h0, h1);
        *reinterpret_cast<__half2*>(&g_cat2_h[off + 2]) = __half2(h2, h3);
    }
}

// ---------------- output LayerNorm ---------------------------------------------
__global__ __launch_bounds__(256) void k_ln_out(const float* __restrict__ go,
                                                const float* __restrict__ bo,
                                                float* __restrict__ out) {
    const int r = blockIdx.x;
    const float* x = g_new + (size_t)r * DM;
    const int tid = threadIdx.x;
    __shared__ float s1[8], s2[8];

    float4 v = reinterpret_cast<const float4*>(x)[tid];
    float sum = v.x + v.y + v.z + v.w;
    float sq  = v.x*v.x + v.y*v.y + v.z*v.z + v.w*v.w;
    sum = warpSum(sum); sq = warpSum(sq);
    if ((tid & 31) == 0) { s1[tid >> 5] = sum; s2[tid >> 5] = sq; }
    __syncthreads();
    sum = 0.f; sq = 0.f;
#pragma unroll
    for (int i = 0; i < 8; ++i) { sum += s1[i]; sq += s2[i]; }
    const float mean = sum * (1.0f / DM);
    const float var  = sq * (1.0f / DM) - mean * mean;
    const float inv  = rsqrtf(var + 1e-5f);

    float4 gv = reinterpret_cast<const float4*>(go)[tid];
    float4 bv = reinterpret_cast<const float4*>(bo)[tid];
    float4 y;
    y.x = (v.x - mean) * inv * gv.x + bv.x;
    y.y = (v.y - mean) * inv * gv.y + bv.y;
    y.z = (v.z - mean) * inv * gv.z + bv.z;
    y.w = (v.w - mean) * inv * gv.w + bv.w;
    reinterpret_cast<float4*>(out + (size_t)r * DM)[tid] = y;
}

// ---------------- launch ---------------------------------------------------------
extern "C" void kernel_launch(void* const* d_in, const int* in_sizes, int n_in,
                              void* d_out, int out_size) {
    (void)in_sizes; (void)n_in; (void)out_size;
    const float* prev = (const float*)d_in[0];
    const float* toks = (const float*)d_in[1];
    const float* Wp   = (const float*)d_in[2];
    const float* bp   = (const float*)d_in[3];
    const float* gs   = (const float*)d_in[4];
    const float* bs   = (const float*)d_in[5];
    const float* gi   = (const float*)d_in[6];
    const float* bi   = (const float*)d_in[7];
    const float* go   = (const float*)d_in[8];
    const float* bo   = (const float*)d_in[9];
    const float* Wu   = (const float*)d_in[10];
    const float* bu   = (const float*)d_in[11];
    const float* Wr   = (const float*)d_in[12];
    const float* br   = (const float*)d_in[13];
    const float* Wn   = (const float*)d_in[14];
    const float* bn   = (const float*)d_in[15];
    float* out = (float*)d_out;

    __half *tok_h, *ps_h, *Wp_h, *Wg_h, *th, *ah, *ch, *c2h;
    cudaGetSymbolAddress((void**)&tok_h, g_tokens_h);
    cudaGetSymbolAddress((void**)&ps_h,  g_ps_h);
    cudaGetSymbolAddress((void**)&Wp_h,  g_Wp_h);
    cudaGetSymbolAddress((void**)&Wg_h,  g_Wg_h);
    cudaGetSymbolAddress((void**)&th,  g_tok_h);
    cudaGetSymbolAddress((void**)&ah,  g_attn_h);
    cudaGetSymbolAddress((void**)&ch,  g_cat_h);
    cudaGetSymbolAddress((void**)&c2h, g_cat2_h);

    // dynamic smem sizes (bytes), 3-stage
    constexpr int SM_BIG    = (3*128*40 + 3*32*136) * 2;   // 56832 (128x128, BT=false)
    constexpr int SM_SCORES = (3*64*40  + 3*128*40) * 2;   // 46080 (64x128, BT=true)
    constexpr int SM_SMALL  = (3*64*40  + 3*32*136) * 2;   // 41472 (64x128, BT=false)
    cudaFuncSetAttribute((const void*)gemm1<128,128,64,32,false,0>,  cudaFuncAttributeMaxDynamicSharedMemorySize, SM_BIG);
    cudaFuncSetAttribute((const void*)gemm1<64,128,32,32,true,1>,    cudaFuncAttributeMaxDynamicSharedMemorySize, SM_SCORES);
    cudaFuncSetAttribute((const void*)gemm1<64,128,32,32,false,2>,   cudaFuncAttributeMaxDynamicSharedMemorySize, SM_SMALL);
    cudaFuncSetAttribute((const void*)gemm1<128,128,64,32,false,34>, cudaFuncAttributeMaxDynamicSharedMemorySize, SM_BIG);
    cudaFuncSetAttribute((const void*)gemm1<64,128,32,32,false,5>,   cudaFuncAttributeMaxDynamicSharedMemorySize, SM_SMALL);

    const long long WSTRIDE = (long long)2 * DM * DM;

    // 1) all fp32->fp16 conversions in ONE launch
    k_convert<<<NB_TOK + NB_PS + NB_WP + 3*NB_WG, 256>>>(
        toks, prev, Wp, Wu, Wr, Wn, tok_h, ps_h, Wp_h, Wg_h);

    // 2) proj: tok = tokens @ W_proj + b   (M=32768,N=1024,K=768) NN
    gemm1<128,128,64,32,false,0><<<dim3(DM/128, (B_*SQ)/128, 1), 256, SM_BIG>>>(
        tok_h, Wp_h, TK, DM, TK, 0, 0, 0, bp, nullptr, nullptr);

    // 3) scores: ps @ tok^T (per batch, M=64,N=2048,K=1024) TN
    gemm1<64,128,32,32,true,1><<<dim3(SQ/128, 1, B_), 256, SM_SCORES>>>(
        ps_h, th, DM, DM, DM,
        (long long)NS*DM, (long long)SQ*DM, NS, nullptr, nullptr, nullptr);

    // 4) softmax -> attn fp16
    k_softmax<<<B_*NS, 256>>>();

    // 5) routed: attn @ tok (per batch, M=64,N=1024,K=2048) NN
    gemm1<64,128,32,32,false,2><<<dim3(DM/128, 1, B_), 256, SM_SMALL>>>(
        ah, th, SQ, DM, SQ,
        (long long)NS*SQ, (long long)SQ*DM, NS, nullptr, nullptr, nullptr);

    // 6) LN(prev), LN(routed) -> cat / cat2
    k_ln_cat<<<2*B_*NS, 256>>>(prev, gs, bs, gi, bi);

    // 7) gates u (z=0) and r (z=1) in ONE launch (M=1024,N=1024,K=2048) NN
    gemm1<128,128,64,32,false,34><<<dim3(DM/128, (B_*NS)/128, 2), 256, SM_BIG>>>(
        ch, Wg_h, 2*DM, DM, 2*DM, 0, WSTRIDE, 0, bu, br, nullptr);

    // 8) cand + gated combine (BM=64 -> 128 CTAs fills the chip)
    gemm1<64,128,32,32,false,5><<<dim3(DM/128, (B_*NS)/64, 1), 256, SM_SMALL>>>(
        c2h, Wg_h + 2*WSTRIDE, 2*DM, DM, 2*DM, 0, 0, 0, bn, nullptr, prev);

    // 9) output LN
    k_ln_out<<<B_*NS, 256>>>(go, bo, out);
}